// round 9
// baseline (speedup 1.0000x reference)
#include <cuda_runtime.h>
#include <cuda_bf16.h>
#include <math.h>
#include <stdint.h>

// Problem constants
#define D_MODEL   1024
#define NUM_HEADS 16
#define D_HEAD    64
#define BATCH     4
#define SEQ       2048
#define MTOT      (BATCH * SEQ)   // 8192

// ---------------------------------------------------------------------------
// Scratch (device globals; no dynamic allocation allowed)
// ---------------------------------------------------------------------------
__device__ __nv_bfloat16 g_qh[(size_t)BATCH * NUM_HEADS * SEQ * D_HEAD];
__device__ __nv_bfloat16 g_ql[(size_t)BATCH * NUM_HEADS * SEQ * D_HEAD];
__device__ __nv_bfloat16 g_kh[(size_t)BATCH * NUM_HEADS * SEQ * D_HEAD];
__device__ __nv_bfloat16 g_kl[(size_t)BATCH * NUM_HEADS * SEQ * D_HEAD];
__device__ __nv_bfloat16 g_vh[(size_t)BATCH * NUM_HEADS * SEQ * D_HEAD];
__device__ __nv_bfloat16 g_vl[(size_t)BATCH * NUM_HEADS * SEQ * D_HEAD];
__device__ __nv_bfloat16 g_x_hi[(size_t)MTOT * D_MODEL];
__device__ __nv_bfloat16 g_x_lo[(size_t)MTOT * D_MODEL];
__device__ __nv_bfloat16 g_w_hi[(size_t)4 * D_MODEL * D_MODEL];     // q,k,v,o
__device__ __nv_bfloat16 g_w_lo[(size_t)4 * D_MODEL * D_MODEL];
__device__ __nv_bfloat16 g_attn_hi[(size_t)MTOT * D_MODEL];
__device__ __nv_bfloat16 g_attn_lo[(size_t)MTOT * D_MODEL];
__device__ float g_cos[SEQ * 32];
__device__ float g_sin[SEQ * 32];

// ---------------------------------------------------------------------------
// PTX helpers (base sm_100: cp.async / ldmatrix / mma.sync only)
// ---------------------------------------------------------------------------
__device__ __forceinline__ uint32_t smem_u32(const void* p) {
    uint32_t a;
    asm("{ .reg .u64 t; cvta.to.shared.u64 t, %1; cvt.u32.u64 %0, t; }"
        : "=r"(a) : "l"(p));
    return a;
}
__device__ __forceinline__ void cp16(uint32_t dst, const void* src) {
    asm volatile("cp.async.cg.shared.global [%0], [%1], 16;" :: "r"(dst), "l"(src));
}
__device__ __forceinline__ void cp_commit() { asm volatile("cp.async.commit_group;"); }
__device__ __forceinline__ void cp_wait0()  { asm volatile("cp.async.wait_group 0;"); }

__device__ __forceinline__ void ldsm4(uint32_t a[4], uint32_t addr) {
    asm volatile("ldmatrix.sync.aligned.m8n8.x4.shared.b16 {%0,%1,%2,%3}, [%4];"
                 : "=r"(a[0]), "=r"(a[1]), "=r"(a[2]), "=r"(a[3]) : "r"(addr));
}
__device__ __forceinline__ void ldsm4t(uint32_t a[4], uint32_t addr) {
    asm volatile("ldmatrix.sync.aligned.m8n8.x4.trans.shared.b16 {%0,%1,%2,%3}, [%4];"
                 : "=r"(a[0]), "=r"(a[1]), "=r"(a[2]), "=r"(a[3]) : "r"(addr));
}
// Non-volatile: pure register math, ptxas may schedule freely.
__device__ __forceinline__ void mma_bf16(float c[4], const uint32_t a[4],
                                         uint32_t b0, uint32_t b1) {
    asm("mma.sync.aligned.m16n8k16.row.col.f32.bf16.bf16.f32 "
        "{%0,%1,%2,%3}, {%4,%5,%6,%7}, {%8,%9}, {%0,%1,%2,%3};"
        : "+f"(c[0]), "+f"(c[1]), "+f"(c[2]), "+f"(c[3])
        : "r"(a[0]), "r"(a[1]), "r"(a[2]), "r"(a[3]), "r"(b0), "r"(b1));
}
__device__ __forceinline__ uint32_t pack_bf16(float a, float b) {
    __nv_bfloat162 t;
    t.x = __float2bfloat16(a);
    t.y = __float2bfloat16(b);
    return *(uint32_t*)&t;
}

// ---------------------------------------------------------------------------
// RoPE cos/sin table
// ---------------------------------------------------------------------------
__global__ void rope_table_kernel(const int* __restrict__ pos) {
    int idx = blockIdx.x * blockDim.x + threadIdx.x;
    if (idx >= SEQ * 32) return;
    int s = idx >> 5;
    int i = idx & 31;
    float inv = exp2f(-(float)i * (log2f(10000.0f) / 32.0f));
    float ang = (float)pos[s] * inv;
    g_cos[idx] = cosf(ang);
    g_sin[idx] = sinf(ang);
}

// ---------------------------------------------------------------------------
// fp32 -> (bf16 hi, bf16 lo) split, vectorized
// ---------------------------------------------------------------------------
__device__ __forceinline__ void split_store(const float4 v, __nv_bfloat16* hi,
                                            __nv_bfloat16* lo, size_t i4) {
    __nv_bfloat16 h0 = __float2bfloat16(v.x);
    __nv_bfloat16 h1 = __float2bfloat16(v.y);
    __nv_bfloat16 h2 = __float2bfloat16(v.z);
    __nv_bfloat16 h3 = __float2bfloat16(v.w);
    __nv_bfloat162 hp0; hp0.x = h0; hp0.y = h1;
    __nv_bfloat162 hp1; hp1.x = h2; hp1.y = h3;
    __nv_bfloat162 lp0;
    lp0.x = __float2bfloat16(v.x - __bfloat162float(h0));
    lp0.y = __float2bfloat16(v.y - __bfloat162float(h1));
    __nv_bfloat162 lp1;
    lp1.x = __float2bfloat16(v.z - __bfloat162float(h2));
    lp1.y = __float2bfloat16(v.w - __bfloat162float(h3));
    ((__nv_bfloat162*)hi)[i4 * 2]     = hp0;
    ((__nv_bfloat162*)hi)[i4 * 2 + 1] = hp1;
    ((__nv_bfloat162*)lo)[i4 * 2]     = lp0;
    ((__nv_bfloat162*)lo)[i4 * 2 + 1] = lp1;
}

__global__ void split_x_kernel(const float* __restrict__ src) {
    size_t i = (size_t)blockIdx.x * blockDim.x + threadIdx.x;
    if (i >= (size_t)MTOT * D_MODEL / 4) return;
    split_store(((const float4*)src)[i], g_x_hi, g_x_lo, i);
}

__global__ void split_w_kernel(const float* __restrict__ Wq,
                               const float* __restrict__ Wk,
                               const float* __restrict__ Wv,
                               const float* __restrict__ Wo) {
    const int z = blockIdx.y;   // 0..3
    const float* src = (z == 0) ? Wq : (z == 1) ? Wk : (z == 2) ? Wv : Wo;
    size_t i = (size_t)blockIdx.x * blockDim.x + threadIdx.x;
    if (i >= (size_t)D_MODEL * D_MODEL / 4) return;
    size_t off4 = (size_t)z * D_MODEL * D_MODEL / 4;
    split_store(((const float4*)src)[i], g_w_hi, g_w_lo, off4 + i);
}

// ---------------------------------------------------------------------------
// Tensor-core GEMM via mma.sync bf16 with 3-term split.
// Pipeline: wait(i) -> sync -> ldmatrix ks0 -> issue cp(i+1) -> compute.
// 128x128 CTA tile, 8 warps, K chunks of 32, 2 CTAs/SM.
// mode = mode_base + blockIdx.z: 0=Q(rope+scale) 1=K(rope) 2=V 3=OUT
// ---------------------------------------------------------------------------
#define NCHUNK      32
#define LDS_B       80                  // bytes per 32-elt row (64 data + 16 pad)
#define ARR_BYTES   (128 * LDS_B)       // 10240
#define STAGE_BYTES (4 * ARR_BYTES)     // 40960
#define GEMM_SMEM   (2 * STAGE_BYTES)   // 81920 -> 2 CTAs/SM

__global__ __launch_bounds__(256, 2) void mma_gemm_kernel(float* __restrict__ outPtr,
                                                          int mode_base)
{
    extern __shared__ char smem[];
    const uint32_t sb = smem_u32(smem);
    const int tid = threadIdx.x;
    const int lane = tid & 31;
    const int warp = tid >> 5;
    const int mode = mode_base + (int)blockIdx.z;
    const int m0 = blockIdx.y * 128;
    const int n0 = blockIdx.x * 128;

    const __nv_bfloat16* Ahi = (mode < 3) ? g_x_hi : g_attn_hi;
    const __nv_bfloat16* Alo = (mode < 3) ? g_x_lo : g_attn_lo;
    const __nv_bfloat16* Bhi = g_w_hi + (size_t)mode * D_MODEL * D_MODEL;
    const __nv_bfloat16* Blo = g_w_lo + (size_t)mode * D_MODEL * D_MODEL;

    const int arr = tid >> 6;                 // 0=Ahi 1=Alo 2=Bhi 3=Blo
    const int tt  = tid & 63;
    const __nv_bfloat16* srcBase = (arr == 0) ? Ahi : (arr == 1) ? Alo
                                  : (arr == 2) ? Bhi : Blo;
    const int rbase = (arr < 2) ? m0 : n0;

    auto issue_chunk = [&](int chunk, int stage) {
        const uint32_t sdst = sb + stage * STAGE_BYTES + arr * ARR_BYTES;
        const int k0 = chunk * 32;
#pragma unroll
        for (int j = 0; j < 8; j++) {
            int idx = tt + j * 64;            // 0..511
            int row = idx >> 2;               // 0..127
            int blk = idx & 3;                // 16B block within row
            const void* g = srcBase + (size_t)(rbase + row) * D_MODEL + k0 + blk * 8;
            cp16(sdst + (uint32_t)(row * LDS_B + blk * 16), g);
        }
    };

    const int warpM = (warp & 1) * 64;
    const int warpN = (warp >> 1) * 32;

    const uint32_t aoff = (uint32_t)((warpM + (lane & 15)) * LDS_B + ((lane >> 4) << 4));
    const uint32_t boff = (uint32_t)((warpN + (lane & 7) + ((lane >> 4) << 3)) * LDS_B
                                     + (((lane >> 3) & 1) << 4));

    float acc[4][4][4];
#pragma unroll
    for (int mf = 0; mf < 4; mf++)
#pragma unroll
        for (int nf = 0; nf < 4; nf++)
#pragma unroll
            for (int c = 0; c < 4; c++) acc[mf][nf][c] = 0.0f;

    issue_chunk(0, 0);
    cp_commit();

    for (int i = 0; i < NCHUNK; i++) {
        const int stage = i & 1;
        cp_wait0();
        __syncthreads();

        const uint32_t base = sb + stage * STAGE_BYTES;
        const uint32_t aHiB = base + aoff;
        const uint32_t aLoB = base + ARR_BYTES + aoff;
        const uint32_t bHiB = base + 2 * ARR_BYTES + boff;
        const uint32_t bLoB = base + 3 * ARR_BYTES + boff;

        // ks0 fragment loads FIRST: their LDS latency hides under the
        // cp.async issue burst for chunk i+1 that follows.
        uint32_t ah[4][4], al[4][4], bh[2][4], bl[2][4];
#pragma unroll
        for (int mf = 0; mf < 4; mf++) {
            ldsm4(ah[mf], aHiB + (uint32_t)(mf * 16 * LDS_B));
            ldsm4(al[mf], aLoB + (uint32_t)(mf * 16 * LDS_B));
        }
#pragma unroll
        for (int np = 0; np < 2; np++) {
            ldsm4(bh[np], bHiB + (uint32_t)(np * 16 * LDS_B));
            ldsm4(bl[np], bLoB + (uint32_t)(np * 16 * LDS_B));
        }

        if (i + 1 < NCHUNK) {
            issue_chunk(i + 1, (i + 1) & 1);
            cp_commit();
        }

#pragma unroll
        for (int ks = 0; ks < 2; ks++) {
            if (ks == 1) {
                const uint32_t kb = 32;
#pragma unroll
                for (int mf = 0; mf < 4; mf++) {
                    ldsm4(ah[mf], aHiB + (uint32_t)(mf * 16 * LDS_B) + kb);
                    ldsm4(al[mf], aLoB + (uint32_t)(mf * 16 * LDS_B) + kb);
                }
#pragma unroll
                for (int np = 0; np < 2; np++) {
                    ldsm4(bh[np], bHiB + (uint32_t)(np * 16 * LDS_B) + kb);
                    ldsm4(bl[np], bLoB + (uint32_t)(np * 16 * LDS_B) + kb);
                }
            }
#pragma unroll
            for (int mf = 0; mf < 4; mf++)
#pragma unroll
                for (int nf = 0; nf < 4; nf++) {
                    const int np = nf >> 1, sub = (nf & 1) * 2;
                    mma_bf16(acc[mf][nf], ah[mf], bh[np][sub], bh[np][sub + 1]);
                    mma_bf16(acc[mf][nf], ah[mf], bl[np][sub], bl[np][sub + 1]);
                    mma_bf16(acc[mf][nf], al[mf], bh[np][sub], bh[np][sub + 1]);
                }
        }
    }

    // Epilogue. Frag: c0,c1 -> (row=lane/4, col=(lane%4)*2,+1); c2,c3 -> row+8.
#pragma unroll
    for (int mf = 0; mf < 4; mf++) {
#pragma unroll
        for (int nf = 0; nf < 4; nf++) {
            const int m = m0 + warpM + mf * 16 + (lane >> 2);
            const int n = n0 + warpN + nf * 8 + (lane & 3) * 2;
#pragma unroll
            for (int half = 0; half < 2; half++) {
                const int mm = m + half * 8;
                float v0 = acc[mf][nf][half * 2];
                float v1 = acc[mf][nf][half * 2 + 1];
                if (mode == 3) {
                    *(float2*)(outPtr + (size_t)mm * D_MODEL + n) = make_float2(v0, v1);
                } else {
                    const int b = mm >> 11;
                    const int s = mm & 2047;
                    const int h = n >> 6;
                    const int dh = n & 63;
                    if (mode < 2) {
                        const int pi = dh >> 1;
                        float co = g_cos[s * 32 + pi];
                        float sn = g_sin[s * 32 + pi];
                        float r0 = v0 * co - v1 * sn;
                        float r1 = v0 * sn + v1 * co;
                        v0 = r0; v1 = r1;
                    }
                    if (mode == 0) { v0 *= 0.125f; v1 *= 0.125f; }  // 1/sqrt(64)
                    __nv_bfloat16 h0 = __float2bfloat16(v0);
                    __nv_bfloat16 h1 = __float2bfloat16(v1);
                    __nv_bfloat162 hp; hp.x = h0; hp.y = h1;
                    __nv_bfloat162 lp;
                    lp.x = __float2bfloat16(v0 - __bfloat162float(h0));
                    lp.y = __float2bfloat16(v1 - __bfloat162float(h1));
                    __nv_bfloat16* hiA = (mode == 0) ? g_qh : (mode == 1) ? g_kh : g_vh;
                    __nv_bfloat16* loA = (mode == 0) ? g_ql : (mode == 1) ? g_kl : g_vl;
                    size_t o = ((size_t)(b * NUM_HEADS + h) * SEQ + s) * D_HEAD + dh;
                    *(__nv_bfloat162*)&hiA[o] = hp;
                    *(__nv_bfloat162*)&loA[o] = lp;
                }
            }
        }
    }
}

// ---------------------------------------------------------------------------
// Tensor-core causal flash attention, 64 q-rows per CTA (128 threads, 4 warps)
// -> ~20K regs/CTA, 92KB smem/CTA -> 2 CTAs/SM WITHOUT register capping.
// Single diagonal tile per CTA. Single-barrier cp.async pipeline.
// ---------------------------------------------------------------------------
#define ATT_LDS   144
#define ATT_ARR   (64 * ATT_LDS)        // 9216
#define ATT_STAGE (4 * ATT_ARR)         // 36864: Kh,Kl,Vh,Vl
#define ATT_Q     (2 * ATT_STAGE)       // 73728
#define ATT_QL    (ATT_Q + 64 * ATT_LDS)
#define ATT_SMEM  (ATT_QL + 64 * ATT_LDS)   // 92160 -> 2 CTAs/SM

__global__ __launch_bounds__(128) void attn_mma_kernel() {
    extern __shared__ char smem[];
    const uint32_t sb = smem_u32(smem);
    const int tid = threadIdx.x;
    const int lane = tid & 31;
    const int warp = tid >> 5;            // 0..3
    const int bh = blockIdx.y;
    const int qtile = (int)gridDim.x - 1 - (int)blockIdx.x;   // longest first
    const int q0 = qtile * 64;

    const size_t bhoff = (size_t)bh * SEQ * D_HEAD;
    const __nv_bfloat16* qhB = g_qh + bhoff;
    const __nv_bfloat16* qlB = g_ql + bhoff;

    // Stage Q: 64 rows x 128B, hi+lo (512 16B units each; 128 threads x 4)
#pragma unroll
    for (int j = 0; j < 4; j++) {
        int idx = tid + j * 128;
        int row = idx >> 3, blk = idx & 7;
        cp16(sb + ATT_Q  + (uint32_t)(row * ATT_LDS + blk * 16),
             qhB + (size_t)(q0 + row) * D_HEAD + blk * 8);
        cp16(sb + ATT_QL + (uint32_t)(row * ATT_LDS + blk * 16),
             qlB + (size_t)(q0 + row) * D_HEAD + blk * 8);
    }

    // K/V loader: 4 arrays x 32 threads, 16 x 16B per thread per tile
    const int arr = tid >> 5;
    const int tt  = tid & 31;
    const __nv_bfloat16* kvsrc =
        ((arr == 0) ? g_kh : (arr == 1) ? g_kl : (arr == 2) ? g_vh : g_vl) + bhoff;
    auto issue_kv = [&](int t, int stage) {
        const uint32_t dst = sb + (uint32_t)(stage * ATT_STAGE + arr * ATT_ARR);
        const int k0 = t * 64;
#pragma unroll
        for (int j = 0; j < 16; j++) {
            int idx = tt + j * 32;
            int row = idx >> 3, blk = idx & 7;
            cp16(dst + (uint32_t)(row * ATT_LDS + blk * 16),
                 kvsrc + (size_t)(k0 + row) * D_HEAD + blk * 8);
        }
    };
    issue_kv(0, 0);
    cp_commit();          // one group: Q + KV0

    cp_wait0();
    __syncthreads();

    // Q fragments (persist): 4 k16 steps, hi+lo
    uint32_t qfh[4][4], qfl[4][4];
    const uint32_t aoff = (uint32_t)((warp * 16 + (lane & 15)) * ATT_LDS
                                     + ((lane >> 4) << 4));
#pragma unroll
    for (int ks = 0; ks < 4; ks++) {
        ldsm4(qfh[ks], sb + ATT_Q  + aoff + ks * 32);
        ldsm4(qfl[ks], sb + ATT_QL + aoff + ks * 32);
    }

    float o[8][4];
#pragma unroll
    for (int nf = 0; nf < 8; nf++)
#pragma unroll
        for (int c = 0; c < 4; c++) o[nf][c] = 0.0f;
    float m0 = -1e30f, m1 = -1e30f, l0 = 0.0f, l1 = 0.0f;

    const int fullTiles = q0 >> 6;
    const int nTiles = fullTiles + 1;     // exactly one diagonal tile
    const int rw0 = q0 + warp * 16 + (lane >> 2);

    const uint32_t boffK = (uint32_t)(((lane & 7) + ((lane >> 4) << 3)) * ATT_LDS
                                      + (((lane >> 3) & 1) << 4));
    const uint32_t voff  = (uint32_t)((lane & 15) * ATT_LDS + ((lane >> 4) << 4));

    for (int t = 0; t < nTiles; t++) {
        const int stage = t & 1;
        const int k0 = t * 64;
        if (t > 0) {
            cp_wait0();
            __syncthreads();
        }
        if (t + 1 < nTiles) {
            issue_kv(t + 1, (t + 1) & 1);
            cp_commit();
        }

        {
            const uint32_t khS = sb + (uint32_t)(stage * ATT_STAGE);
            const uint32_t klS = khS + ATT_ARR;
            const uint32_t vhS = khS + 2 * ATT_ARR;
            const uint32_t vlS = khS + 3 * ATT_ARR;

            // ---- S = Q K^T (3-term) ----
            float s[8][4];
#pragma unroll
            for (int nf = 0; nf < 8; nf++)
#pragma unroll
                for (int c = 0; c < 4; c++) s[nf][c] = 0.0f;

#pragma unroll
            for (int ks = 0; ks < 4; ks++) {
                uint32_t kh4[4][4], kl4[4][4];
#pragma unroll
                for (int np = 0; np < 4; np++) {
                    ldsm4(kh4[np], khS + (uint32_t)(np * 16 * ATT_LDS) + ks * 32 + boffK);
                    ldsm4(kl4[np], klS + (uint32_t)(np * 16 * ATT_LDS) + ks * 32 + boffK);
                }
#pragma unroll
                for (int np = 0; np < 4; np++) {
                    mma_bf16(s[np * 2],     qfh[ks], kh4[np][0], kh4[np][1]);
                    mma_bf16(s[np * 2 + 1], qfh[ks], kh4[np][2], kh4[np][3]);
                    mma_bf16(s[np * 2],     qfh[ks], kl4[np][0], kl4[np][1]);
                    mma_bf16(s[np * 2 + 1], qfh[ks], kl4[np][2], kl4[np][3]);
                    mma_bf16(s[np * 2],     qfl[ks], kh4[np][0], kh4[np][1]);
                    mma_bf16(s[np * 2 + 1], qfl[ks], kh4[np][2], kh4[np][3]);
                }
            }

            // ---- causal mask (diagonal tile only) ----
            if (t == fullTiles) {
#pragma unroll
                for (int nf = 0; nf < 8; nf++) {
                    int kg = k0 + nf * 8 + (lane & 3) * 2;
#pragma unroll
                    for (int c = 0; c < 4; c++) {
                        int kk = kg + (c & 1);
                        int qq = rw0 + ((c >> 1) << 3);
                        if (kk > qq) s[nf][c] = -1e30f;
                    }
                }
            }

            // ---- online softmax ----
            float mx0 = s[0][0], mx1 = s[0][2];
#pragma unroll
            for (int nf = 0; nf < 8; nf++) {
                mx0 = fmaxf(mx0, fmaxf(s[nf][0], s[nf][1]));
                mx1 = fmaxf(mx1, fmaxf(s[nf][2], s[nf][3]));
            }
            mx0 = fmaxf(mx0, __shfl_xor_sync(0xFFFFFFFFu, mx0, 1));
            mx0 = fmaxf(mx0, __shfl_xor_sync(0xFFFFFFFFu, mx0, 2));
            mx1 = fmaxf(mx1, __shfl_xor_sync(0xFFFFFFFFu, mx1, 1));
            mx1 = fmaxf(mx1, __shfl_xor_sync(0xFFFFFFFFu, mx1, 2));
            float nm0 = fmaxf(m0, mx0), nm1 = fmaxf(m1, mx1);
            float al0 = __expf(m0 - nm0), al1 = __expf(m1 - nm1);
            m0 = nm0; m1 = nm1;
            l0 *= al0; l1 *= al1;
#pragma unroll
            for (int nf = 0; nf < 8; nf++) {
                o[nf][0] *= al0; o[nf][1] *= al0;
                o[nf][2] *= al1; o[nf][3] *= al1;
            }

            float rs0 = 0.0f, rs1 = 0.0f;
            uint32_t ph[4][4], pl[4][4];
#pragma unroll
            for (int nf = 0; nf < 8; nf++) {
                float p0 = __expf(s[nf][0] - m0);
                float p1 = __expf(s[nf][1] - m0);
                float p2 = __expf(s[nf][2] - m1);
                float p3 = __expf(s[nf][3] - m1);
                rs0 += p0 + p1;
                rs1 += p2 + p3;
                const int ks = nf >> 1, i0 = (nf & 1) * 2;
                uint32_t h01 = pack_bf16(p0, p1);
                uint32_t h23 = pack_bf16(p2, p3);
                ph[ks][i0]     = h01;
                ph[ks][i0 + 1] = h23;
                __nv_bfloat162 hb01 = *(__nv_bfloat162*)&h01;
                __nv_bfloat162 hb23 = *(__nv_bfloat162*)&h23;
                pl[ks][i0]     = pack_bf16(p0 - __bfloat162float(hb01.x),
                                           p1 - __bfloat162float(hb01.y));
                pl[ks][i0 + 1] = pack_bf16(p2 - __bfloat162float(hb23.x),
                                           p3 - __bfloat162float(hb23.y));
            }
            rs0 += __shfl_xor_sync(0xFFFFFFFFu, rs0, 1);
            rs0 += __shfl_xor_sync(0xFFFFFFFFu, rs0, 2);
            rs1 += __shfl_xor_sync(0xFFFFFFFFu, rs1, 1);
            rs1 += __shfl_xor_sync(0xFFFFFFFFu, rs1, 2);
            l0 += rs0; l1 += rs1;

            // ---- O += P V (3-term; V via trans ldmatrix) ----
#pragma unroll
            for (int ks = 0; ks < 4; ks++) {
                uint32_t vh4[4][4], vl4[4][4];
#pragma unroll
                for (int np = 0; np < 4; np++) {
                    ldsm4t(vh4[np], vhS + (uint32_t)(ks * 16 * ATT_LDS) + np * 32 + voff);
                    ldsm4t(vl4[np], vlS + (uint32_t)(ks * 16 * ATT_LDS) + np * 32 + voff);
                }
#pragma unroll
                for (int np = 0; np < 4; np++) {
                    mma_bf16(o[np * 2],     ph[ks], vh4[np][0], vh4[np][1]);
                    mma_bf16(o[np * 2 + 1], ph[ks], vh4[np][2], vh4[np][3]);
                    mma_bf16(o[np * 2],     ph[ks], vl4[np][0], vl4[np][1]);
                    mma_bf16(o[np * 2 + 1], ph[ks], vl4[np][2], vl4[np][3]);
                    mma_bf16(o[np * 2],     pl[ks], vh4[np][0], vh4[np][1]);
                    mma_bf16(o[np * 2 + 1], pl[ks], vh4[np][2], vh4[np][3]);
                }
            }
        }
    }

    // ---- epilogue: normalize, bf16 hi/lo split into [B,S,H*64] ----
    float inv0 = 1.0f / l0, inv1 = 1.0f / l1;
    const int b = bh >> 4, h = bh & 15;
    const int r0 = q0 + warp * 16 + (lane >> 2);
    const size_t base0 = ((size_t)(b * SEQ + r0)) * D_MODEL + h * D_HEAD + (lane & 3) * 2;
    const size_t base1 = base0 + (size_t)8 * D_MODEL;
#pragma unroll
    for (int nf = 0; nf < 8; nf++) {
        float a0 = o[nf][0] * inv0, a1 = o[nf][1] * inv0;
        float b0 = o[nf][2] * inv1, b1 = o[nf][3] * inv1;
        uint32_t ha = pack_bf16(a0, a1);
        uint32_t hb = pack_bf16(b0, b1);
        __nv_bfloat162 hba = *(__nv_bfloat162*)&ha;
        __nv_bfloat162 hbb = *(__nv_bfloat162*)&hb;
        uint32_t la = pack_bf16(a0 - __bfloat162float(hba.x), a1 - __bfloat162float(hba.y));
        uint32_t lb = pack_bf16(b0 - __bfloat162float(hbb.x), b1 - __bfloat162float(hbb.y));
        *(uint32_t*)&g_attn_hi[base0 + nf * 8] = ha;
        *(uint32_t*)&g_attn_lo[base0 + nf * 8] = la;
        *(uint32_t*)&g_attn_hi[base1 + nf * 8] = hb;
        *(uint32_t*)&g_attn_lo[base1 + nf * 8] = lb;
    }
}

// ---------------------------------------------------------------------------
// Launch
// ---------------------------------------------------------------------------
extern "C" void kernel_launch(void* const* d_in, const int* in_sizes, int n_in,
                              void* d_out, int out_size)
{
    const float* x   = (const float*)d_in[0];
    const int*   pos = (const int*)  d_in[1];
    const float* Wq  = (const float*)d_in[2];
    const float* Wk  = (const float*)d_in[3];
    const float* Wv  = (const float*)d_in[4];
    const float* Wo  = (const float*)d_in[5];
    float* out = (float*)d_out;

    cudaFuncSetAttribute(mma_gemm_kernel,
                         cudaFuncAttributeMaxDynamicSharedMemorySize, GEMM_SMEM);
    cudaFuncSetAttribute(attn_mma_kernel,
                         cudaFuncAttributeMaxDynamicSharedMemorySize, ATT_SMEM);

    rope_table_kernel<<<(SEQ * 32 + 255) / 256, 256>>>(pos);

    split_x_kernel<<<(MTOT * D_MODEL / 4 + 255) / 256, 256>>>(x);
    dim3 gw((D_MODEL * D_MODEL / 4 + 255) / 256, 4);
    split_w_kernel<<<gw, 256>>>(Wq, Wk, Wv, Wo);

    dim3 gq(D_MODEL / 128, MTOT / 128, 3);       // Q,K,V projections
    mma_gemm_kernel<<<gq, 256, GEMM_SMEM>>>(out, 0);

    dim3 ga(SEQ / 64, BATCH * NUM_HEADS);        // 64 q-rows per CTA
    attn_mma_kernel<<<ga, 128, ATT_SMEM>>>();

    dim3 go(D_MODEL / 128, MTOT / 128, 1);       // output projection
    mma_gemm_kernel<<<go, 256, GEMM_SMEM>>>(out, 3);
}

// round 10
// speedup vs baseline: 1.2464x; 1.2464x over previous
#include <cuda_runtime.h>
#include <cuda_bf16.h>
#include <math.h>
#include <stdint.h>

// Problem constants
#define D_MODEL   1024
#define NUM_HEADS 16
#define D_HEAD    64
#define BATCH     4
#define SEQ       2048
#define MTOT      (BATCH * SEQ)   // 8192

// ---------------------------------------------------------------------------
// Scratch (device globals; no dynamic allocation allowed)
// ---------------------------------------------------------------------------
__device__ __nv_bfloat16 g_qh[(size_t)BATCH * NUM_HEADS * SEQ * D_HEAD];
__device__ __nv_bfloat16 g_ql[(size_t)BATCH * NUM_HEADS * SEQ * D_HEAD];
__device__ __nv_bfloat16 g_kh[(size_t)BATCH * NUM_HEADS * SEQ * D_HEAD];
__device__ __nv_bfloat16 g_kl[(size_t)BATCH * NUM_HEADS * SEQ * D_HEAD];
__device__ __nv_bfloat16 g_vh[(size_t)BATCH * NUM_HEADS * SEQ * D_HEAD];
__device__ __nv_bfloat16 g_vl[(size_t)BATCH * NUM_HEADS * SEQ * D_HEAD];
__device__ float g_xt[(size_t)MTOT * D_MODEL];                    // tf32-rounded x
__device__ float g_wt[(size_t)4 * D_MODEL * D_MODEL];             // tf32 q,k,v,o
__device__ float g_attn[(size_t)MTOT * D_MODEL];                  // tf32-rounded
__device__ float g_cos[SEQ * 32];
__device__ float g_sin[SEQ * 32];

// ---------------------------------------------------------------------------
// PTX helpers (base sm_100: cp.async / ldmatrix / mma.sync only)
// ---------------------------------------------------------------------------
__device__ __forceinline__ uint32_t smem_u32(const void* p) {
    uint32_t a;
    asm("{ .reg .u64 t; cvta.to.shared.u64 t, %1; cvt.u32.u64 %0, t; }"
        : "=r"(a) : "l"(p));
    return a;
}
__device__ __forceinline__ void cp16(uint32_t dst, const void* src) {
    asm volatile("cp.async.cg.shared.global [%0], [%1], 16;" :: "r"(dst), "l"(src));
}
__device__ __forceinline__ void cp_commit() { asm volatile("cp.async.commit_group;"); }
__device__ __forceinline__ void cp_wait0()  { asm volatile("cp.async.wait_group 0;"); }

__device__ __forceinline__ void ldsm4(uint32_t a[4], uint32_t addr) {
    asm volatile("ldmatrix.sync.aligned.m8n8.x4.shared.b16 {%0,%1,%2,%3}, [%4];"
                 : "=r"(a[0]), "=r"(a[1]), "=r"(a[2]), "=r"(a[3]) : "r"(addr));
}
__device__ __forceinline__ void ldsm4t(uint32_t a[4], uint32_t addr) {
    asm volatile("ldmatrix.sync.aligned.m8n8.x4.trans.shared.b16 {%0,%1,%2,%3}, [%4];"
                 : "=r"(a[0]), "=r"(a[1]), "=r"(a[2]), "=r"(a[3]) : "r"(addr));
}
// bf16 mma (attention)
__device__ __forceinline__ void mma_bf16(float c[4], const uint32_t a[4],
                                         uint32_t b0, uint32_t b1) {
    asm("mma.sync.aligned.m16n8k16.row.col.f32.bf16.bf16.f32 "
        "{%0,%1,%2,%3}, {%4,%5,%6,%7}, {%8,%9}, {%0,%1,%2,%3};"
        : "+f"(c[0]), "+f"(c[1]), "+f"(c[2]), "+f"(c[3])
        : "r"(a[0]), "r"(a[1]), "r"(a[2]), "r"(a[3]), "r"(b0), "r"(b1));
}
// tf32 mma (projections); operands pre-rounded with cvt.rna
__device__ __forceinline__ void mma_tf32(float c[4], const uint32_t a[4],
                                         uint32_t b0, uint32_t b1) {
    asm("mma.sync.aligned.m16n8k8.row.col.f32.tf32.tf32.f32 "
        "{%0,%1,%2,%3}, {%4,%5,%6,%7}, {%8,%9}, {%0,%1,%2,%3};"
        : "+f"(c[0]), "+f"(c[1]), "+f"(c[2]), "+f"(c[3])
        : "r"(a[0]), "r"(a[1]), "r"(a[2]), "r"(a[3]), "r"(b0), "r"(b1));
}
__device__ __forceinline__ uint32_t pack_bf16(float a, float b) {
    __nv_bfloat162 t;
    t.x = __float2bfloat16(a);
    t.y = __float2bfloat16(b);
    return *(uint32_t*)&t;
}
__device__ __forceinline__ float tf32r(float x) {
    uint32_t u;
    asm("cvt.rna.tf32.f32 %0, %1;" : "=r"(u) : "f"(x));
    return __uint_as_float(u);
}

// ---------------------------------------------------------------------------
// RoPE cos/sin table
// ---------------------------------------------------------------------------
__global__ void rope_table_kernel(const int* __restrict__ pos) {
    int idx = blockIdx.x * blockDim.x + threadIdx.x;
    if (idx >= SEQ * 32) return;
    int s = idx >> 5;
    int i = idx & 31;
    float inv = exp2f(-(float)i * (log2f(10000.0f) / 32.0f));
    float ang = (float)pos[s] * inv;
    g_cos[idx] = cosf(ang);
    g_sin[idx] = sinf(ang);
}

// ---------------------------------------------------------------------------
// fp32 -> tf32-rounded fp32 (rna), vectorized
// ---------------------------------------------------------------------------
__global__ void round_x_kernel(const float* __restrict__ src) {
    size_t i = (size_t)blockIdx.x * blockDim.x + threadIdx.x;
    if (i >= (size_t)MTOT * D_MODEL / 4) return;
    float4 v = ((const float4*)src)[i];
    v.x = tf32r(v.x); v.y = tf32r(v.y); v.z = tf32r(v.z); v.w = tf32r(v.w);
    ((float4*)g_xt)[i] = v;
}

__global__ void round_w_kernel(const float* __restrict__ Wq,
                               const float* __restrict__ Wk,
                               const float* __restrict__ Wv,
                               const float* __restrict__ Wo) {
    const int z = blockIdx.y;   // 0..3
    const float* src = (z == 0) ? Wq : (z == 1) ? Wk : (z == 2) ? Wv : Wo;
    size_t i = (size_t)blockIdx.x * blockDim.x + threadIdx.x;
    if (i >= (size_t)D_MODEL * D_MODEL / 4) return;
    float4 v = ((const float4*)src)[i];
    v.x = tf32r(v.x); v.y = tf32r(v.y); v.z = tf32r(v.z); v.w = tf32r(v.w);
    ((float4*)g_wt)[(size_t)z * D_MODEL * D_MODEL / 4 + i] = v;
}

// ---------------------------------------------------------------------------
// Tensor-core GEMM via single-pass TF32 mma.sync.
// C[m,n] = sum_k A[m,k]*B[n,k]. 128x128 CTA tile, 8 warps (2m x 4n),
// K chunks of 32 fp32 (128B rows + 16B pad), double-buffered, 2 CTAs/SM.
// mode = mode_base + blockIdx.z: 0=Q(rope+scale) 1=K(rope) 2=V 3=OUT
// ---------------------------------------------------------------------------
#define NCHUNK      32
#define LDS_B       144                 // 128B data + 16B pad
#define ARR_BYTES   (128 * LDS_B)       // 18432
#define STAGE_BYTES (2 * ARR_BYTES)     // 36864 (A, B)
#define GEMM_SMEM   (2 * STAGE_BYTES)   // 73728 -> 2 CTAs/SM

__global__ __launch_bounds__(256, 2) void mma_gemm_kernel(float* __restrict__ outPtr,
                                                          int mode_base)
{
    extern __shared__ char smem[];
    const uint32_t sb = smem_u32(smem);
    const int tid = threadIdx.x;
    const int lane = tid & 31;
    const int warp = tid >> 5;
    const int mode = mode_base + (int)blockIdx.z;
    const int m0 = blockIdx.y * 128;
    const int n0 = blockIdx.x * 128;

    const float* Asrc = (mode < 3) ? g_xt : g_attn;
    const float* Bsrc = g_wt + (size_t)mode * D_MODEL * D_MODEL;

    const int arr = tid >> 7;                 // 0=A 1=B (128 threads each)
    const int tt  = tid & 127;
    const float* srcBase = arr ? Bsrc : Asrc;
    const int rbase = arr ? n0 : m0;

    // Per chunk per array: 128 rows x 128B = 1024 x 16B; 128 thr x 8 cp16
    auto issue_chunk = [&](int chunk, int stage) {
        const uint32_t sdst = sb + stage * STAGE_BYTES + arr * ARR_BYTES;
        const int k0 = chunk * 32;
#pragma unroll
        for (int j = 0; j < 8; j++) {
            int idx = tt + j * 128;           // 0..1023
            int row = idx >> 3;               // 0..127
            int blk = idx & 7;                // 16B block (4 fp32)
            const void* g = srcBase + (size_t)(rbase + row) * D_MODEL + k0 + blk * 4;
            cp16(sdst + (uint32_t)(row * LDS_B + blk * 16), g);
        }
    };

    const int warpM = (warp & 1) * 64;
    const int warpN = (warp >> 1) * 32;

    // Same ldmatrix address patterns as bf16 (8-row x 16B tiles):
    const uint32_t aoff = (uint32_t)((warpM + (lane & 15)) * LDS_B + ((lane >> 4) << 4));
    const uint32_t boff = (uint32_t)((warpN + (lane & 7) + ((lane >> 4) << 3)) * LDS_B
                                     + (((lane >> 3) & 1) << 4));

    float acc[4][4][4];
#pragma unroll
    for (int mf = 0; mf < 4; mf++)
#pragma unroll
        for (int nf = 0; nf < 4; nf++)
#pragma unroll
            for (int c = 0; c < 4; c++) acc[mf][nf][c] = 0.0f;

    issue_chunk(0, 0);
    cp_commit();

    for (int i = 0; i < NCHUNK; i++) {
        const int stage = i & 1;
        cp_wait0();
        __syncthreads();

        const uint32_t aB = sb + stage * STAGE_BYTES + aoff;
        const uint32_t bB = sb + stage * STAGE_BYTES + ARR_BYTES + boff;

        // ks0 fragments first; their latency hides under the cp burst below.
        uint32_t a4[4][4], b4[2][4];
#pragma unroll
        for (int mf = 0; mf < 4; mf++) ldsm4(a4[mf], aB + (uint32_t)(mf * 16 * LDS_B));
#pragma unroll
        for (int np = 0; np < 2; np++)  ldsm4(b4[np], bB + (uint32_t)(np * 16 * LDS_B));

        if (i + 1 < NCHUNK) {
            issue_chunk(i + 1, (i + 1) & 1);
            cp_commit();
        }

#pragma unroll
        for (int ks = 0; ks < 4; ks++) {     // k8 per step, 32B stride
            if (ks > 0) {
                const uint32_t kb = (uint32_t)(ks * 32);
#pragma unroll
                for (int mf = 0; mf < 4; mf++)
                    ldsm4(a4[mf], aB + (uint32_t)(mf * 16 * LDS_B) + kb);
#pragma unroll
                for (int np = 0; np < 2; np++)
                    ldsm4(b4[np], bB + (uint32_t)(np * 16 * LDS_B) + kb);
            }
#pragma unroll
            for (int mf = 0; mf < 4; mf++)
#pragma unroll
                for (int nf = 0; nf < 4; nf++) {
                    const int np = nf >> 1, sub = (nf & 1) * 2;
                    mma_tf32(acc[mf][nf], a4[mf], b4[np][sub], b4[np][sub + 1]);
                }
        }
    }

    // Epilogue. Frag: c0,c1 -> (row=lane/4, col=(lane%4)*2,+1); c2,c3 -> row+8.
#pragma unroll
    for (int mf = 0; mf < 4; mf++) {
#pragma unroll
        for (int nf = 0; nf < 4; nf++) {
            const int m = m0 + warpM + mf * 16 + (lane >> 2);
            const int n = n0 + warpN + nf * 8 + (lane & 3) * 2;
#pragma unroll
            for (int half = 0; half < 2; half++) {
                const int mm = m + half * 8;
                float v0 = acc[mf][nf][half * 2];
                float v1 = acc[mf][nf][half * 2 + 1];
                if (mode == 3) {
                    *(float2*)(outPtr + (size_t)mm * D_MODEL + n) = make_float2(v0, v1);
                } else {
                    const int b = mm >> 11;
                    const int s = mm & 2047;
                    const int h = n >> 6;
                    const int dh = n & 63;
                    if (mode < 2) {
                        const int pi = dh >> 1;
                        float co = g_cos[s * 32 + pi];
                        float sn = g_sin[s * 32 + pi];
                        float r0 = v0 * co - v1 * sn;
                        float r1 = v0 * sn + v1 * co;
                        v0 = r0; v1 = r1;
                    }
                    if (mode == 0) { v0 *= 0.125f; v1 *= 0.125f; }  // 1/sqrt(64)
                    __nv_bfloat16 h0 = __float2bfloat16(v0);
                    __nv_bfloat16 h1 = __float2bfloat16(v1);
                    __nv_bfloat162 hp; hp.x = h0; hp.y = h1;
                    __nv_bfloat162 lp;
                    lp.x = __float2bfloat16(v0 - __bfloat162float(h0));
                    lp.y = __float2bfloat16(v1 - __bfloat162float(h1));
                    __nv_bfloat16* hiA = (mode == 0) ? g_qh : (mode == 1) ? g_kh : g_vh;
                    __nv_bfloat16* loA = (mode == 0) ? g_ql : (mode == 1) ? g_kl : g_vl;
                    size_t o = ((size_t)(b * NUM_HEADS + h) * SEQ + s) * D_HEAD + dh;
                    *(__nv_bfloat162*)&hiA[o] = hp;
                    *(__nv_bfloat162*)&loA[o] = lp;
                }
            }
        }
    }
}

// ---------------------------------------------------------------------------
// Tensor-core causal flash attention, 64 q-rows per CTA (128 threads, 4 warps),
// 3-term bf16 split, single-barrier cp.async pipeline, 2 CTAs/SM.
// Epilogue writes tf32-rounded fp32 attn (for the TF32 O-projection).
// ---------------------------------------------------------------------------
#define ATT_LDS   144
#define ATT_ARR   (64 * ATT_LDS)        // 9216
#define ATT_STAGE (4 * ATT_ARR)         // 36864: Kh,Kl,Vh,Vl
#define ATT_Q     (2 * ATT_STAGE)       // 73728
#define ATT_QL    (ATT_Q + 64 * ATT_LDS)
#define ATT_SMEM  (ATT_QL + 64 * ATT_LDS)   // 92160 -> 2 CTAs/SM

__global__ __launch_bounds__(128) void attn_mma_kernel() {
    extern __shared__ char smem[];
    const uint32_t sb = smem_u32(smem);
    const int tid = threadIdx.x;
    const int lane = tid & 31;
    const int warp = tid >> 5;            // 0..3
    const int bh = blockIdx.y;
    const int qtile = (int)gridDim.x - 1 - (int)blockIdx.x;   // longest first
    const int q0 = qtile * 64;

    const size_t bhoff = (size_t)bh * SEQ * D_HEAD;
    const __nv_bfloat16* qhB = g_qh + bhoff;
    const __nv_bfloat16* qlB = g_ql + bhoff;

    // Stage Q: 64 rows x 128B, hi+lo
#pragma unroll
    for (int j = 0; j < 4; j++) {
        int idx = tid + j * 128;
        int row = idx >> 3, blk = idx & 7;
        cp16(sb + ATT_Q  + (uint32_t)(row * ATT_LDS + blk * 16),
             qhB + (size_t)(q0 + row) * D_HEAD + blk * 8);
        cp16(sb + ATT_QL + (uint32_t)(row * ATT_LDS + blk * 16),
             qlB + (size_t)(q0 + row) * D_HEAD + blk * 8);
    }

    const int arr = tid >> 5;
    const int tt  = tid & 31;
    const __nv_bfloat16* kvsrc =
        ((arr == 0) ? g_kh : (arr == 1) ? g_kl : (arr == 2) ? g_vh : g_vl) + bhoff;
    auto issue_kv = [&](int t, int stage) {
        const uint32_t dst = sb + (uint32_t)(stage * ATT_STAGE + arr * ATT_ARR);
        const int k0 = t * 64;
#pragma unroll
        for (int j = 0; j < 16; j++) {
            int idx = tt + j * 32;
            int row = idx >> 3, blk = idx & 7;
            cp16(dst + (uint32_t)(row * ATT_LDS + blk * 16),
                 kvsrc + (size_t)(k0 + row) * D_HEAD + blk * 8);
        }
    };
    issue_kv(0, 0);
    cp_commit();

    cp_wait0();
    __syncthreads();

    uint32_t qfh[4][4], qfl[4][4];
    const uint32_t aoff = (uint32_t)((warp * 16 + (lane & 15)) * ATT_LDS
                                     + ((lane >> 4) << 4));
#pragma unroll
    for (int ks = 0; ks < 4; ks++) {
        ldsm4(qfh[ks], sb + ATT_Q  + aoff + ks * 32);
        ldsm4(qfl[ks], sb + ATT_QL + aoff + ks * 32);
    }

    float o[8][4];
#pragma unroll
    for (int nf = 0; nf < 8; nf++)
#pragma unroll
        for (int c = 0; c < 4; c++) o[nf][c] = 0.0f;
    float m0 = -1e30f, m1 = -1e30f, l0 = 0.0f, l1 = 0.0f;

    const int fullTiles = q0 >> 6;
    const int nTiles = fullTiles + 1;
    const int rw0 = q0 + warp * 16 + (lane >> 2);

    const uint32_t boffK = (uint32_t)(((lane & 7) + ((lane >> 4) << 3)) * ATT_LDS
                                      + (((lane >> 3) & 1) << 4));
    const uint32_t voff  = (uint32_t)((lane & 15) * ATT_LDS + ((lane >> 4) << 4));

    for (int t = 0; t < nTiles; t++) {
        const int stage = t & 1;
        const int k0 = t * 64;
        if (t > 0) {
            cp_wait0();
            __syncthreads();
        }
        if (t + 1 < nTiles) {
            issue_kv(t + 1, (t + 1) & 1);
            cp_commit();
        }

        {
            const uint32_t khS = sb + (uint32_t)(stage * ATT_STAGE);
            const uint32_t klS = khS + ATT_ARR;
            const uint32_t vhS = khS + 2 * ATT_ARR;
            const uint32_t vlS = khS + 3 * ATT_ARR;

            // ---- S = Q K^T (3-term) ----
            float s[8][4];
#pragma unroll
            for (int nf = 0; nf < 8; nf++)
#pragma unroll
                for (int c = 0; c < 4; c++) s[nf][c] = 0.0f;

#pragma unroll
            for (int ks = 0; ks < 4; ks++) {
                uint32_t kh4[4][4], kl4[4][4];
#pragma unroll
                for (int np = 0; np < 4; np++) {
                    ldsm4(kh4[np], khS + (uint32_t)(np * 16 * ATT_LDS) + ks * 32 + boffK);
                    ldsm4(kl4[np], klS + (uint32_t)(np * 16 * ATT_LDS) + ks * 32 + boffK);
                }
#pragma unroll
                for (int np = 0; np < 4; np++) {
                    mma_bf16(s[np * 2],     qfh[ks], kh4[np][0], kh4[np][1]);
                    mma_bf16(s[np * 2 + 1], qfh[ks], kh4[np][2], kh4[np][3]);
                    mma_bf16(s[np * 2],     qfh[ks], kl4[np][0], kl4[np][1]);
                    mma_bf16(s[np * 2 + 1], qfh[ks], kl4[np][2], kl4[np][3]);
                    mma_bf16(s[np * 2],     qfl[ks], kh4[np][0], kh4[np][1]);
                    mma_bf16(s[np * 2 + 1], qfl[ks], kh4[np][2], kh4[np][3]);
                }
            }

            // ---- causal mask (diagonal tile only) ----
            if (t == fullTiles) {
#pragma unroll
                for (int nf = 0; nf < 8; nf++) {
                    int kg = k0 + nf * 8 + (lane & 3) * 2;
#pragma unroll
                    for (int c = 0; c < 4; c++) {
                        int kk = kg + (c & 1);
                        int qq = rw0 + ((c >> 1) << 3);
                        if (kk > qq) s[nf][c] = -1e30f;
                    }
                }
            }

            // ---- online softmax ----
            float mx0 = s[0][0], mx1 = s[0][2];
#pragma unroll
            for (int nf = 0; nf < 8; nf++) {
                mx0 = fmaxf(mx0, fmaxf(s[nf][0], s[nf][1]));
                mx1 = fmaxf(mx1, fmaxf(s[nf][2], s[nf][3]));
            }
            mx0 = fmaxf(mx0, __shfl_xor_sync(0xFFFFFFFFu, mx0, 1));
            mx0 = fmaxf(mx0, __shfl_xor_sync(0xFFFFFFFFu, mx0, 2));
            mx1 = fmaxf(mx1, __shfl_xor_sync(0xFFFFFFFFu, mx1, 1));
            mx1 = fmaxf(mx1, __shfl_xor_sync(0xFFFFFFFFu, mx1, 2));
            float nm0 = fmaxf(m0, mx0), nm1 = fmaxf(m1, mx1);
            float al0 = __expf(m0 - nm0), al1 = __expf(m1 - nm1);
            m0 = nm0; m1 = nm1;
            l0 *= al0; l1 *= al1;
#pragma unroll
            for (int nf = 0; nf < 8; nf++) {
                o[nf][0] *= al0; o[nf][1] *= al0;
                o[nf][2] *= al1; o[nf][3] *= al1;
            }

            float rs0 = 0.0f, rs1 = 0.0f;
            uint32_t ph[4][4], pl[4][4];
#pragma unroll
            for (int nf = 0; nf < 8; nf++) {
                float p0 = __expf(s[nf][0] - m0);
                float p1 = __expf(s[nf][1] - m0);
                float p2 = __expf(s[nf][2] - m1);
                float p3 = __expf(s[nf][3] - m1);
                rs0 += p0 + p1;
                rs1 += p2 + p3;
                const int ks = nf >> 1, i0 = (nf & 1) * 2;
                uint32_t h01 = pack_bf16(p0, p1);
                uint32_t h23 = pack_bf16(p2, p3);
                ph[ks][i0]     = h01;
                ph[ks][i0 + 1] = h23;
                __nv_bfloat162 hb01 = *(__nv_bfloat162*)&h01;
                __nv_bfloat162 hb23 = *(__nv_bfloat162*)&h23;
                pl[ks][i0]     = pack_bf16(p0 - __bfloat162float(hb01.x),
                                           p1 - __bfloat162float(hb01.y));
                pl[ks][i0 + 1] = pack_bf16(p2 - __bfloat162float(hb23.x),
                                           p3 - __bfloat162float(hb23.y));
            }
            rs0 += __shfl_xor_sync(0xFFFFFFFFu, rs0, 1);
            rs0 += __shfl_xor_sync(0xFFFFFFFFu, rs0, 2);
            rs1 += __shfl_xor_sync(0xFFFFFFFFu, rs1, 1);
            rs1 += __shfl_xor_sync(0xFFFFFFFFu, rs1, 2);
            l0 += rs0; l1 += rs1;

            // ---- O += P V (3-term; V via trans ldmatrix) ----
#pragma unroll
            for (int ks = 0; ks < 4; ks++) {
                uint32_t vh4[4][4], vl4[4][4];
#pragma unroll
                for (int np = 0; np < 4; np++) {
                    ldsm4t(vh4[np], vhS + (uint32_t)(ks * 16 * ATT_LDS) + np * 32 + voff);
                    ldsm4t(vl4[np], vlS + (uint32_t)(ks * 16 * ATT_LDS) + np * 32 + voff);
                }
#pragma unroll
                for (int np = 0; np < 4; np++) {
                    mma_bf16(o[np * 2],     ph[ks], vh4[np][0], vh4[np][1]);
                    mma_bf16(o[np * 2 + 1], ph[ks], vh4[np][2], vh4[np][3]);
                    mma_bf16(o[np * 2],     ph[ks], vl4[np][0], vl4[np][1]);
                    mma_bf16(o[np * 2 + 1], ph[ks], vl4[np][2], vl4[np][3]);
                    mma_bf16(o[np * 2],     pl[ks], vh4[np][0], vh4[np][1]);
                    mma_bf16(o[np * 2 + 1], pl[ks], vh4[np][2], vh4[np][3]);
                }
            }
        }
    }

    // ---- epilogue: normalize, tf32-round, store fp32 attn [B,S,H*64] ----
    float inv0 = 1.0f / l0, inv1 = 1.0f / l1;
    const int b = bh >> 4, h = bh & 15;
    const int r0 = q0 + warp * 16 + (lane >> 2);
    const size_t base0 = ((size_t)(b * SEQ + r0)) * D_MODEL + h * D_HEAD + (lane & 3) * 2;
    const size_t base1 = base0 + (size_t)8 * D_MODEL;
#pragma unroll
    for (int nf = 0; nf < 8; nf++) {
        float2 va = make_float2(tf32r(o[nf][0] * inv0), tf32r(o[nf][1] * inv0));
        float2 vb = make_float2(tf32r(o[nf][2] * inv1), tf32r(o[nf][3] * inv1));
        *(float2*)&g_attn[base0 + nf * 8] = va;
        *(float2*)&g_attn[base1 + nf * 8] = vb;
    }
}

// ---------------------------------------------------------------------------
// Launch
// ---------------------------------------------------------------------------
extern "C" void kernel_launch(void* const* d_in, const int* in_sizes, int n_in,
                              void* d_out, int out_size)
{
    const float* x   = (const float*)d_in[0];
    const int*   pos = (const int*)  d_in[1];
    const float* Wq  = (const float*)d_in[2];
    const float* Wk  = (const float*)d_in[3];
    const float* Wv  = (const float*)d_in[4];
    const float* Wo  = (const float*)d_in[5];
    float* out = (float*)d_out;

    cudaFuncSetAttribute(mma_gemm_kernel,
                         cudaFuncAttributeMaxDynamicSharedMemorySize, GEMM_SMEM);
    cudaFuncSetAttribute(attn_mma_kernel,
                         cudaFuncAttributeMaxDynamicSharedMemorySize, ATT_SMEM);

    rope_table_kernel<<<(SEQ * 32 + 255) / 256, 256>>>(pos);

    round_x_kernel<<<(MTOT * D_MODEL / 4 + 255) / 256, 256>>>(x);
    dim3 gw((D_MODEL * D_MODEL / 4 + 255) / 256, 4);
    round_w_kernel<<<gw, 256>>>(Wq, Wk, Wv, Wo);

    dim3 gq(D_MODEL / 128, MTOT / 128, 3);       // Q,K,V projections
    mma_gemm_kernel<<<gq, 256, GEMM_SMEM>>>(out, 0);

    dim3 ga(SEQ / 64, BATCH * NUM_HEADS);        // 64 q-rows per CTA
    attn_mma_kernel<<<ga, 128, ATT_SMEM>>>();

    dim3 go(D_MODEL / 128, MTOT / 128, 1);       // output projection
    mma_gemm_kernel<<<go, 256, GEMM_SMEM>>>(out, 3);
}

// round 11
// speedup vs baseline: 1.2686x; 1.0178x over previous
#include <cuda_runtime.h>
#include <cuda_bf16.h>
#include <math.h>
#include <stdint.h>

// Problem constants
#define D_MODEL   1024
#define NUM_HEADS 16
#define D_HEAD    64
#define BATCH     4
#define SEQ       2048
#define MTOT      (BATCH * SEQ)   // 8192

// ---------------------------------------------------------------------------
// Scratch (device globals; no dynamic allocation allowed)
// ---------------------------------------------------------------------------
__device__ __nv_bfloat16 g_qh[(size_t)BATCH * NUM_HEADS * SEQ * D_HEAD];
__device__ __nv_bfloat16 g_ql[(size_t)BATCH * NUM_HEADS * SEQ * D_HEAD];
__device__ __nv_bfloat16 g_kh[(size_t)BATCH * NUM_HEADS * SEQ * D_HEAD];
__device__ __nv_bfloat16 g_kl[(size_t)BATCH * NUM_HEADS * SEQ * D_HEAD];
__device__ __nv_bfloat16 g_vh[(size_t)BATCH * NUM_HEADS * SEQ * D_HEAD];
__device__ __nv_bfloat16 g_vl[(size_t)BATCH * NUM_HEADS * SEQ * D_HEAD];
__device__ float g_xt[(size_t)MTOT * D_MODEL];                    // tf32-rounded x
__device__ float g_wt[(size_t)4 * D_MODEL * D_MODEL];             // tf32 q,k,v,o
__device__ float g_attn[(size_t)MTOT * D_MODEL];                  // tf32-rounded
__device__ float g_cos[SEQ * 32];
__device__ float g_sin[SEQ * 32];

// ---------------------------------------------------------------------------
// PTX helpers (base sm_100: cp.async / ldmatrix / mma.sync only)
// ---------------------------------------------------------------------------
__device__ __forceinline__ uint32_t smem_u32(const void* p) {
    uint32_t a;
    asm("{ .reg .u64 t; cvta.to.shared.u64 t, %1; cvt.u32.u64 %0, t; }"
        : "=r"(a) : "l"(p));
    return a;
}
__device__ __forceinline__ void cp16(uint32_t dst, const void* src) {
    asm volatile("cp.async.cg.shared.global [%0], [%1], 16;" :: "r"(dst), "l"(src));
}
__device__ __forceinline__ void cp_commit() { asm volatile("cp.async.commit_group;"); }
__device__ __forceinline__ void cp_wait0()  { asm volatile("cp.async.wait_group 0;"); }

__device__ __forceinline__ void ldsm4(uint32_t a[4], uint32_t addr) {
    asm volatile("ldmatrix.sync.aligned.m8n8.x4.shared.b16 {%0,%1,%2,%3}, [%4];"
                 : "=r"(a[0]), "=r"(a[1]), "=r"(a[2]), "=r"(a[3]) : "r"(addr));
}
__device__ __forceinline__ void ldsm4t(uint32_t a[4], uint32_t addr) {
    asm volatile("ldmatrix.sync.aligned.m8n8.x4.trans.shared.b16 {%0,%1,%2,%3}, [%4];"
                 : "=r"(a[0]), "=r"(a[1]), "=r"(a[2]), "=r"(a[3]) : "r"(addr));
}
// bf16 mma (attention)
__device__ __forceinline__ void mma_bf16(float c[4], const uint32_t a[4],
                                         uint32_t b0, uint32_t b1) {
    asm("mma.sync.aligned.m16n8k16.row.col.f32.bf16.bf16.f32 "
        "{%0,%1,%2,%3}, {%4,%5,%6,%7}, {%8,%9}, {%0,%1,%2,%3};"
        : "+f"(c[0]), "+f"(c[1]), "+f"(c[2]), "+f"(c[3])
        : "r"(a[0]), "r"(a[1]), "r"(a[2]), "r"(a[3]), "r"(b0), "r"(b1));
}
// tf32 mma (projections); operands pre-rounded with cvt.rna
__device__ __forceinline__ void mma_tf32(float c[4], const uint32_t a[4],
                                         uint32_t b0, uint32_t b1) {
    asm("mma.sync.aligned.m16n8k8.row.col.f32.tf32.tf32.f32 "
        "{%0,%1,%2,%3}, {%4,%5,%6,%7}, {%8,%9}, {%0,%1,%2,%3};"
        : "+f"(c[0]), "+f"(c[1]), "+f"(c[2]), "+f"(c[3])
        : "r"(a[0]), "r"(a[1]), "r"(a[2]), "r"(a[3]), "r"(b0), "r"(b1));
}
__device__ __forceinline__ uint32_t pack_bf16(float a, float b) {
    __nv_bfloat162 t;
    t.x = __float2bfloat16(a);
    t.y = __float2bfloat16(b);
    return *(uint32_t*)&t;
}
__device__ __forceinline__ float tf32r(float x) {
    uint32_t u;
    asm("cvt.rna.tf32.f32 %0, %1;" : "=r"(u) : "f"(x));
    return __uint_as_float(u);
}

// ---------------------------------------------------------------------------
// RoPE cos/sin table
// ---------------------------------------------------------------------------
__global__ void rope_table_kernel(const int* __restrict__ pos) {
    int idx = blockIdx.x * blockDim.x + threadIdx.x;
    if (idx >= SEQ * 32) return;
    int s = idx >> 5;
    int i = idx & 31;
    float inv = exp2f(-(float)i * (log2f(10000.0f) / 32.0f));
    float ang = (float)pos[s] * inv;
    g_cos[idx] = cosf(ang);
    g_sin[idx] = sinf(ang);
}

// ---------------------------------------------------------------------------
// fp32 -> tf32-rounded fp32 (rna), vectorized
// ---------------------------------------------------------------------------
__global__ void round_x_kernel(const float* __restrict__ src) {
    size_t i = (size_t)blockIdx.x * blockDim.x + threadIdx.x;
    if (i >= (size_t)MTOT * D_MODEL / 4) return;
    float4 v = ((const float4*)src)[i];
    v.x = tf32r(v.x); v.y = tf32r(v.y); v.z = tf32r(v.z); v.w = tf32r(v.w);
    ((float4*)g_xt)[i] = v;
}

__global__ void round_w_kernel(const float* __restrict__ Wq,
                               const float* __restrict__ Wk,
                               const float* __restrict__ Wv,
                               const float* __restrict__ Wo) {
    const int z = blockIdx.y;   // 0..3
    const float* src = (z == 0) ? Wq : (z == 1) ? Wk : (z == 2) ? Wv : Wo;
    size_t i = (size_t)blockIdx.x * blockDim.x + threadIdx.x;
    if (i >= (size_t)D_MODEL * D_MODEL / 4) return;
    float4 v = ((const float4*)src)[i];
    v.x = tf32r(v.x); v.y = tf32r(v.y); v.z = tf32r(v.z); v.w = tf32r(v.w);
    ((float4*)g_wt)[(size_t)z * D_MODEL * D_MODEL / 4 + i] = v;
}

// ---------------------------------------------------------------------------
// Tensor-core GEMM via single-pass TF32 mma.sync (unchanged from R10).
// ---------------------------------------------------------------------------
#define NCHUNK      32
#define LDS_B       144                 // 128B data + 16B pad
#define ARR_BYTES   (128 * LDS_B)       // 18432
#define STAGE_BYTES (2 * ARR_BYTES)     // 36864 (A, B)
#define GEMM_SMEM   (2 * STAGE_BYTES)   // 73728 -> 2 CTAs/SM

__global__ __launch_bounds__(256, 2) void mma_gemm_kernel(float* __restrict__ outPtr,
                                                          int mode_base)
{
    extern __shared__ char smem[];
    const uint32_t sb = smem_u32(smem);
    const int tid = threadIdx.x;
    const int lane = tid & 31;
    const int warp = tid >> 5;
    const int mode = mode_base + (int)blockIdx.z;
    const int m0 = blockIdx.y * 128;
    const int n0 = blockIdx.x * 128;

    const float* Asrc = (mode < 3) ? g_xt : g_attn;
    const float* Bsrc = g_wt + (size_t)mode * D_MODEL * D_MODEL;

    const int arr = tid >> 7;                 // 0=A 1=B
    const int tt  = tid & 127;
    const float* srcBase = arr ? Bsrc : Asrc;
    const int rbase = arr ? n0 : m0;

    auto issue_chunk = [&](int chunk, int stage) {
        const uint32_t sdst = sb + stage * STAGE_BYTES + arr * ARR_BYTES;
        const int k0 = chunk * 32;
#pragma unroll
        for (int j = 0; j < 8; j++) {
            int idx = tt + j * 128;
            int row = idx >> 3;
            int blk = idx & 7;
            const void* g = srcBase + (size_t)(rbase + row) * D_MODEL + k0 + blk * 4;
            cp16(sdst + (uint32_t)(row * LDS_B + blk * 16), g);
        }
    };

    const int warpM = (warp & 1) * 64;
    const int warpN = (warp >> 1) * 32;

    const uint32_t aoff = (uint32_t)((warpM + (lane & 15)) * LDS_B + ((lane >> 4) << 4));
    const uint32_t boff = (uint32_t)((warpN + (lane & 7) + ((lane >> 4) << 3)) * LDS_B
                                     + (((lane >> 3) & 1) << 4));

    float acc[4][4][4];
#pragma unroll
    for (int mf = 0; mf < 4; mf++)
#pragma unroll
        for (int nf = 0; nf < 4; nf++)
#pragma unroll
            for (int c = 0; c < 4; c++) acc[mf][nf][c] = 0.0f;

    issue_chunk(0, 0);
    cp_commit();

    for (int i = 0; i < NCHUNK; i++) {
        const int stage = i & 1;
        cp_wait0();
        __syncthreads();

        const uint32_t aB = sb + stage * STAGE_BYTES + aoff;
        const uint32_t bB = sb + stage * STAGE_BYTES + ARR_BYTES + boff;

        uint32_t a4[4][4], b4[2][4];
#pragma unroll
        for (int mf = 0; mf < 4; mf++) ldsm4(a4[mf], aB + (uint32_t)(mf * 16 * LDS_B));
#pragma unroll
        for (int np = 0; np < 2; np++)  ldsm4(b4[np], bB + (uint32_t)(np * 16 * LDS_B));

        if (i + 1 < NCHUNK) {
            issue_chunk(i + 1, (i + 1) & 1);
            cp_commit();
        }

#pragma unroll
        for (int ks = 0; ks < 4; ks++) {
            if (ks > 0) {
                const uint32_t kb = (uint32_t)(ks * 32);
#pragma unroll
                for (int mf = 0; mf < 4; mf++)
                    ldsm4(a4[mf], aB + (uint32_t)(mf * 16 * LDS_B) + kb);
#pragma unroll
                for (int np = 0; np < 2; np++)
                    ldsm4(b4[np], bB + (uint32_t)(np * 16 * LDS_B) + kb);
            }
#pragma unroll
            for (int mf = 0; mf < 4; mf++)
#pragma unroll
                for (int nf = 0; nf < 4; nf++) {
                    const int np = nf >> 1, sub = (nf & 1) * 2;
                    mma_tf32(acc[mf][nf], a4[mf], b4[np][sub], b4[np][sub + 1]);
                }
        }
    }

#pragma unroll
    for (int mf = 0; mf < 4; mf++) {
#pragma unroll
        for (int nf = 0; nf < 4; nf++) {
            const int m = m0 + warpM + mf * 16 + (lane >> 2);
            const int n = n0 + warpN + nf * 8 + (lane & 3) * 2;
#pragma unroll
            for (int half = 0; half < 2; half++) {
                const int mm = m + half * 8;
                float v0 = acc[mf][nf][half * 2];
                float v1 = acc[mf][nf][half * 2 + 1];
                if (mode == 3) {
                    *(float2*)(outPtr + (size_t)mm * D_MODEL + n) = make_float2(v0, v1);
                } else {
                    const int b = mm >> 11;
                    const int s = mm & 2047;
                    const int h = n >> 6;
                    const int dh = n & 63;
                    if (mode < 2) {
                        const int pi = dh >> 1;
                        float co = g_cos[s * 32 + pi];
                        float sn = g_sin[s * 32 + pi];
                        float r0 = v0 * co - v1 * sn;
                        float r1 = v0 * sn + v1 * co;
                        v0 = r0; v1 = r1;
                    }
                    if (mode == 0) { v0 *= 0.125f; v1 *= 0.125f; }  // 1/sqrt(64)
                    __nv_bfloat16 h0 = __float2bfloat16(v0);
                    __nv_bfloat16 h1 = __float2bfloat16(v1);
                    __nv_bfloat162 hp; hp.x = h0; hp.y = h1;
                    __nv_bfloat162 lp;
                    lp.x = __float2bfloat16(v0 - __bfloat162float(h0));
                    lp.y = __float2bfloat16(v1 - __bfloat162float(h1));
                    __nv_bfloat16* hiA = (mode == 0) ? g_qh : (mode == 1) ? g_kh : g_vh;
                    __nv_bfloat16* loA = (mode == 0) ? g_ql : (mode == 1) ? g_kl : g_vl;
                    size_t o = ((size_t)(b * NUM_HEADS + h) * SEQ + s) * D_HEAD + dh;
                    *(__nv_bfloat162*)&hiA[o] = hp;
                    *(__nv_bfloat162*)&loA[o] = lp;
                }
            }
        }
    }
}

// ---------------------------------------------------------------------------
// Tensor-core causal flash attention, 64 q-rows per CTA (128 threads, 4 warps),
// 3-term bf16 split. Q is staged THROUGH the KV stage-0 buffer (no separate Q
// area) -> 73.7KB smem -> 3 CTAs/SM (12 warps). Math identical to R10.
// ---------------------------------------------------------------------------
#define ATT_LDS   144
#define ATT_ARR   (64 * ATT_LDS)        // 9216
#define ATT_STAGE (4 * ATT_ARR)         // 36864: Kh,Kl,Vh,Vl
#define ATT_SMEM  (2 * ATT_STAGE)       // 73728 -> 3 CTAs/SM

__global__ __launch_bounds__(128, 3) void attn_mma_kernel() {
    extern __shared__ char smem[];
    const uint32_t sb = smem_u32(smem);
    const int tid = threadIdx.x;
    const int lane = tid & 31;
    const int warp = tid >> 5;            // 0..3
    const int bh = blockIdx.y;
    const int qtile = (int)gridDim.x - 1 - (int)blockIdx.x;   // longest first
    const int q0 = qtile * 64;

    const size_t bhoff = (size_t)bh * SEQ * D_HEAD;
    const __nv_bfloat16* qhB = g_qh + bhoff;
    const __nv_bfloat16* qlB = g_ql + bhoff;

    // ---- Stage Q into KV stage-0 buffer (hi -> Kh area, lo -> Kl area) ----
#pragma unroll
    for (int j = 0; j < 4; j++) {
        int idx = tid + j * 128;
        int row = idx >> 3, blk = idx & 7;
        cp16(sb + (uint32_t)(row * ATT_LDS + blk * 16),
             qhB + (size_t)(q0 + row) * D_HEAD + blk * 8);
        cp16(sb + ATT_ARR + (uint32_t)(row * ATT_LDS + blk * 16),
             qlB + (size_t)(q0 + row) * D_HEAD + blk * 8);
    }
    cp_commit();
    cp_wait0();
    __syncthreads();

    // Q fragments (persist): 4 k16 steps, hi+lo
    uint32_t qfh[4][4], qfl[4][4];
    const uint32_t aoff = (uint32_t)((warp * 16 + (lane & 15)) * ATT_LDS
                                     + ((lane >> 4) << 4));
#pragma unroll
    for (int ks = 0; ks < 4; ks++) {
        ldsm4(qfh[ks], sb + aoff + ks * 32);
        ldsm4(qfl[ks], sb + ATT_ARR + aoff + ks * 32);
    }
    __syncthreads();     // all warps done reading Q before KV0 overwrites it

    // K/V loader: 4 arrays x 32 threads, 16 x 16B per thread per tile
    const int arr = tid >> 5;
    const int tt  = tid & 31;
    const __nv_bfloat16* kvsrc =
        ((arr == 0) ? g_kh : (arr == 1) ? g_kl : (arr == 2) ? g_vh : g_vl) + bhoff;
    auto issue_kv = [&](int t, int stage) {
        const uint32_t dst = sb + (uint32_t)(stage * ATT_STAGE + arr * ATT_ARR);
        const int k0 = t * 64;
#pragma unroll
        for (int j = 0; j < 16; j++) {
            int idx = tt + j * 32;
            int row = idx >> 3, blk = idx & 7;
            cp16(dst + (uint32_t)(row * ATT_LDS + blk * 16),
                 kvsrc + (size_t)(k0 + row) * D_HEAD + blk * 8);
        }
    };
    issue_kv(0, 0);
    cp_commit();

    float o[8][4];
#pragma unroll
    for (int nf = 0; nf < 8; nf++)
#pragma unroll
        for (int c = 0; c < 4; c++) o[nf][c] = 0.0f;
    float m0 = -1e30f, m1 = -1e30f, l0 = 0.0f, l1 = 0.0f;

    const int fullTiles = q0 >> 6;
    const int nTiles = fullTiles + 1;
    const int rw0 = q0 + warp * 16 + (lane >> 2);

    const uint32_t boffK = (uint32_t)(((lane & 7) + ((lane >> 4) << 3)) * ATT_LDS
                                      + (((lane >> 3) & 1) << 4));
    const uint32_t voff  = (uint32_t)((lane & 15) * ATT_LDS + ((lane >> 4) << 4));

    for (int t = 0; t < nTiles; t++) {
        const int stage = t & 1;
        const int k0 = t * 64;
        cp_wait0();
        __syncthreads();
        if (t + 1 < nTiles) {
            issue_kv(t + 1, (t + 1) & 1);
            cp_commit();
        }

        {
            const uint32_t khS = sb + (uint32_t)(stage * ATT_STAGE);
            const uint32_t klS = khS + ATT_ARR;
            const uint32_t vhS = khS + 2 * ATT_ARR;
            const uint32_t vlS = khS + 3 * ATT_ARR;

            // ---- S = Q K^T (3-term) ----
            float s[8][4];
#pragma unroll
            for (int nf = 0; nf < 8; nf++)
#pragma unroll
                for (int c = 0; c < 4; c++) s[nf][c] = 0.0f;

#pragma unroll
            for (int ks = 0; ks < 4; ks++) {
                uint32_t kh4[4][4], kl4[4][4];
#pragma unroll
                for (int np = 0; np < 4; np++) {
                    ldsm4(kh4[np], khS + (uint32_t)(np * 16 * ATT_LDS) + ks * 32 + boffK);
                    ldsm4(kl4[np], klS + (uint32_t)(np * 16 * ATT_LDS) + ks * 32 + boffK);
                }
#pragma unroll
                for (int np = 0; np < 4; np++) {
                    mma_bf16(s[np * 2],     qfh[ks], kh4[np][0], kh4[np][1]);
                    mma_bf16(s[np * 2 + 1], qfh[ks], kh4[np][2], kh4[np][3]);
                    mma_bf16(s[np * 2],     qfh[ks], kl4[np][0], kl4[np][1]);
                    mma_bf16(s[np * 2 + 1], qfh[ks], kl4[np][2], kl4[np][3]);
                    mma_bf16(s[np * 2],     qfl[ks], kh4[np][0], kh4[np][1]);
                    mma_bf16(s[np * 2 + 1], qfl[ks], kh4[np][2], kh4[np][3]);
                }
            }

            // ---- causal mask (diagonal tile only) ----
            if (t == fullTiles) {
#pragma unroll
                for (int nf = 0; nf < 8; nf++) {
                    int kg = k0 + nf * 8 + (lane & 3) * 2;
#pragma unroll
                    for (int c = 0; c < 4; c++) {
                        int kk = kg + (c & 1);
                        int qq = rw0 + ((c >> 1) << 3);
                        if (kk > qq) s[nf][c] = -1e30f;
                    }
                }
            }

            // ---- online softmax ----
            float mx0 = s[0][0], mx1 = s[0][2];
#pragma unroll
            for (int nf = 0; nf < 8; nf++) {
                mx0 = fmaxf(mx0, fmaxf(s[nf][0], s[nf][1]));
                mx1 = fmaxf(mx1, fmaxf(s[nf][2], s[nf][3]));
            }
            mx0 = fmaxf(mx0, __shfl_xor_sync(0xFFFFFFFFu, mx0, 1));
            mx0 = fmaxf(mx0, __shfl_xor_sync(0xFFFFFFFFu, mx0, 2));
            mx1 = fmaxf(mx1, __shfl_xor_sync(0xFFFFFFFFu, mx1, 1));
            mx1 = fmaxf(mx1, __shfl_xor_sync(0xFFFFFFFFu, mx1, 2));
            float nm0 = fmaxf(m0, mx0), nm1 = fmaxf(m1, mx1);
            float al0 = __expf(m0 - nm0), al1 = __expf(m1 - nm1);
            m0 = nm0; m1 = nm1;
            l0 *= al0; l1 *= al1;
#pragma unroll
            for (int nf = 0; nf < 8; nf++) {
                o[nf][0] *= al0; o[nf][1] *= al0;
                o[nf][2] *= al1; o[nf][3] *= al1;
            }

            float rs0 = 0.0f, rs1 = 0.0f;
            uint32_t ph[4][4], pl[4][4];
#pragma unroll
            for (int nf = 0; nf < 8; nf++) {
                float p0 = __expf(s[nf][0] - m0);
                float p1 = __expf(s[nf][1] - m0);
                float p2 = __expf(s[nf][2] - m1);
                float p3 = __expf(s[nf][3] - m1);
                rs0 += p0 + p1;
                rs1 += p2 + p3;
                const int ks = nf >> 1, i0 = (nf & 1) * 2;
                uint32_t h01 = pack_bf16(p0, p1);
                uint32_t h23 = pack_bf16(p2, p3);
                ph[ks][i0]     = h01;
                ph[ks][i0 + 1] = h23;
                __nv_bfloat162 hb01 = *(__nv_bfloat162*)&h01;
                __nv_bfloat162 hb23 = *(__nv_bfloat162*)&h23;
                pl[ks][i0]     = pack_bf16(p0 - __bfloat162float(hb01.x),
                                           p1 - __bfloat162float(hb01.y));
                pl[ks][i0 + 1] = pack_bf16(p2 - __bfloat162float(hb23.x),
                                           p3 - __bfloat162float(hb23.y));
            }
            rs0 += __shfl_xor_sync(0xFFFFFFFFu, rs0, 1);
            rs0 += __shfl_xor_sync(0xFFFFFFFFu, rs0, 2);
            rs1 += __shfl_xor_sync(0xFFFFFFFFu, rs1, 1);
            rs1 += __shfl_xor_sync(0xFFFFFFFFu, rs1, 2);
            l0 += rs0; l1 += rs1;

            // ---- O += P V (3-term; V via trans ldmatrix) ----
#pragma unroll
            for (int ks = 0; ks < 4; ks++) {
                uint32_t vh4[4][4], vl4[4][4];
#pragma unroll
                for (int np = 0; np < 4; np++) {
                    ldsm4t(vh4[np], vhS + (uint32_t)(ks * 16 * ATT_LDS) + np * 32 + voff);
                    ldsm4t(vl4[np], vlS + (uint32_t)(ks * 16 * ATT_LDS) + np * 32 + voff);
                }
#pragma unroll
                for (int np = 0; np < 4; np++) {
                    mma_bf16(o[np * 2],     ph[ks], vh4[np][0], vh4[np][1]);
                    mma_bf16(o[np * 2 + 1], ph[ks], vh4[np][2], vh4[np][3]);
                    mma_bf16(o[np * 2],     ph[ks], vl4[np][0], vl4[np][1]);
                    mma_bf16(o[np * 2 + 1], ph[ks], vl4[np][2], vl4[np][3]);
                    mma_bf16(o[np * 2],     pl[ks], vh4[np][0], vh4[np][1]);
                    mma_bf16(o[np * 2 + 1], pl[ks], vh4[np][2], vh4[np][3]);
                }
            }
        }
    }

    // ---- epilogue: normalize, tf32-round, store fp32 attn [B,S,H*64] ----
    float inv0 = 1.0f / l0, inv1 = 1.0f / l1;
    const int b = bh >> 4, h = bh & 15;
    const int r0 = q0 + warp * 16 + (lane >> 2);
    const size_t base0 = ((size_t)(b * SEQ + r0)) * D_MODEL + h * D_HEAD + (lane & 3) * 2;
    const size_t base1 = base0 + (size_t)8 * D_MODEL;
#pragma unroll
    for (int nf = 0; nf < 8; nf++) {
        float2 va = make_float2(tf32r(o[nf][0] * inv0), tf32r(o[nf][1] * inv0));
        float2 vb = make_float2(tf32r(o[nf][2] * inv1), tf32r(o[nf][3] * inv1));
        *(float2*)&g_attn[base0 + nf * 8] = va;
        *(float2*)&g_attn[base1 + nf * 8] = vb;
    }
}

// ---------------------------------------------------------------------------
// Launch
// ---------------------------------------------------------------------------
extern "C" void kernel_launch(void* const* d_in, const int* in_sizes, int n_in,
                              void* d_out, int out_size)
{
    const float* x   = (const float*)d_in[0];
    const int*   pos = (const int*)  d_in[1];
    const float* Wq  = (const float*)d_in[2];
    const float* Wk  = (const float*)d_in[3];
    const float* Wv  = (const float*)d_in[4];
    const float* Wo  = (const float*)d_in[5];
    float* out = (float*)d_out;

    cudaFuncSetAttribute(mma_gemm_kernel,
                         cudaFuncAttributeMaxDynamicSharedMemorySize, GEMM_SMEM);
    cudaFuncSetAttribute(attn_mma_kernel,
                         cudaFuncAttributeMaxDynamicSharedMemorySize, ATT_SMEM);

    rope_table_kernel<<<(SEQ * 32 + 255) / 256, 256>>>(pos);

    round_x_kernel<<<(MTOT * D_MODEL / 4 + 255) / 256, 256>>>(x);
    dim3 gw((D_MODEL * D_MODEL / 4 + 255) / 256, 4);
    round_w_kernel<<<gw, 256>>>(Wq, Wk, Wv, Wo);

    dim3 gq(D_MODEL / 128, MTOT / 128, 3);       // Q,K,V projections
    mma_gemm_kernel<<<gq, 256, GEMM_SMEM>>>(out, 0);

    dim3 ga(SEQ / 64, BATCH * NUM_HEADS);        // 64 q-rows per CTA
    attn_mma_kernel<<<ga, 128, ATT_SMEM>>>();

    dim3 go(D_MODEL / 128, MTOT / 128, 1);       // output projection
    mma_gemm_kernel<<<go, 256, GEMM_SMEM>>>(out, 3);
}

// round 14
// speedup vs baseline: 1.3239x; 1.0436x over previous
#include <cuda_runtime.h>
#include <cuda_bf16.h>
#include <math.h>
#include <stdint.h>

// Problem constants
#define D_MODEL   1024
#define NUM_HEADS 16
#define D_HEAD    64
#define BATCH     4
#define SEQ       2048
#define MTOT      (BATCH * SEQ)   // 8192

// ---------------------------------------------------------------------------
// Scratch (device globals; no dynamic allocation allowed)
// ---------------------------------------------------------------------------
__device__ float g_qt[(size_t)BATCH * NUM_HEADS * SEQ * D_HEAD];   // tf32 Q
__device__ float g_kt[(size_t)BATCH * NUM_HEADS * SEQ * D_HEAD];   // tf32 K
__device__ __nv_bfloat16 g_vh[(size_t)BATCH * NUM_HEADS * SEQ * D_HEAD];
__device__ __nv_bfloat16 g_vl[(size_t)BATCH * NUM_HEADS * SEQ * D_HEAD];
__device__ float g_xt[(size_t)MTOT * D_MODEL];                    // tf32-rounded x
__device__ float g_wt[(size_t)4 * D_MODEL * D_MODEL];             // tf32 q,k,v,o
__device__ float g_attn[(size_t)MTOT * D_MODEL];                  // tf32-rounded
__device__ float g_cos[SEQ * 32];
__device__ float g_sin[SEQ * 32];

// ---------------------------------------------------------------------------
// PTX helpers (base sm_100: cp.async / ldmatrix / mma.sync only)
// ---------------------------------------------------------------------------
__device__ __forceinline__ uint32_t smem_u32(const void* p) {
    uint32_t a;
    asm("{ .reg .u64 t; cvta.to.shared.u64 t, %1; cvt.u32.u64 %0, t; }"
        : "=r"(a) : "l"(p));
    return a;
}
__device__ __forceinline__ void cp16(uint32_t dst, const void* src) {
    asm volatile("cp.async.cg.shared.global [%0], [%1], 16;" :: "r"(dst), "l"(src));
}
__device__ __forceinline__ void cp_commit() { asm volatile("cp.async.commit_group;"); }
__device__ __forceinline__ void cp_wait0()  { asm volatile("cp.async.wait_group 0;"); }

__device__ __forceinline__ void ldsm4(uint32_t a[4], uint32_t addr) {
    asm volatile("ldmatrix.sync.aligned.m8n8.x4.shared.b16 {%0,%1,%2,%3}, [%4];"
                 : "=r"(a[0]), "=r"(a[1]), "=r"(a[2]), "=r"(a[3]) : "r"(addr));
}
__device__ __forceinline__ void ldsm4t(uint32_t a[4], uint32_t addr) {
    asm volatile("ldmatrix.sync.aligned.m8n8.x4.trans.shared.b16 {%0,%1,%2,%3}, [%4];"
                 : "=r"(a[0]), "=r"(a[1]), "=r"(a[2]), "=r"(a[3]) : "r"(addr));
}
__device__ __forceinline__ void mma_bf16(float c[4], const uint32_t a[4],
                                         uint32_t b0, uint32_t b1) {
    asm("mma.sync.aligned.m16n8k16.row.col.f32.bf16.bf16.f32 "
        "{%0,%1,%2,%3}, {%4,%5,%6,%7}, {%8,%9}, {%0,%1,%2,%3};"
        : "+f"(c[0]), "+f"(c[1]), "+f"(c[2]), "+f"(c[3])
        : "r"(a[0]), "r"(a[1]), "r"(a[2]), "r"(a[3]), "r"(b0), "r"(b1));
}
__device__ __forceinline__ void mma_tf32(float c[4], const uint32_t a[4],
                                         uint32_t b0, uint32_t b1) {
    asm("mma.sync.aligned.m16n8k8.row.col.f32.tf32.tf32.f32 "
        "{%0,%1,%2,%3}, {%4,%5,%6,%7}, {%8,%9}, {%0,%1,%2,%3};"
        : "+f"(c[0]), "+f"(c[1]), "+f"(c[2]), "+f"(c[3])
        : "r"(a[0]), "r"(a[1]), "r"(a[2]), "r"(a[3]), "r"(b0), "r"(b1));
}
__device__ __forceinline__ uint32_t pack_bf16(float a, float b) {
    __nv_bfloat162 t;
    t.x = __float2bfloat16(a);
    t.y = __float2bfloat16(b);
    return *(uint32_t*)&t;
}
__device__ __forceinline__ float tf32r(float x) {
    uint32_t u;
    asm("cvt.rna.tf32.f32 %0, %1;" : "=r"(u) : "f"(x));
    return __uint_as_float(u);
}

// ---------------------------------------------------------------------------
// RoPE cos/sin table
// ---------------------------------------------------------------------------
__global__ void rope_table_kernel(const int* __restrict__ pos) {
    int idx = blockIdx.x * blockDim.x + threadIdx.x;
    if (idx >= SEQ * 32) return;
    int s = idx >> 5;
    int i = idx & 31;
    float inv = exp2f(-(float)i * (log2f(10000.0f) / 32.0f));
    float ang = (float)pos[s] * inv;
    g_cos[idx] = cosf(ang);
    g_sin[idx] = sinf(ang);
}

// ---------------------------------------------------------------------------
// fp32 -> tf32-rounded fp32 (rna), vectorized
// ---------------------------------------------------------------------------
__global__ void round_x_kernel(const float* __restrict__ src) {
    size_t i = (size_t)blockIdx.x * blockDim.x + threadIdx.x;
    if (i >= (size_t)MTOT * D_MODEL / 4) return;
    float4 v = ((const float4*)src)[i];
    v.x = tf32r(v.x); v.y = tf32r(v.y); v.z = tf32r(v.z); v.w = tf32r(v.w);
    ((float4*)g_xt)[i] = v;
}

__global__ void round_w_kernel(const float* __restrict__ Wq,
                               const float* __restrict__ Wk,
                               const float* __restrict__ Wv,
                               const float* __restrict__ Wo) {
    const int z = blockIdx.y;   // 0..3
    const float* src = (z == 0) ? Wq : (z == 1) ? Wk : (z == 2) ? Wv : Wo;
    size_t i = (size_t)blockIdx.x * blockDim.x + threadIdx.x;
    if (i >= (size_t)D_MODEL * D_MODEL / 4) return;
    float4 v = ((const float4*)src)[i];
    v.x = tf32r(v.x); v.y = tf32r(v.y); v.z = tf32r(v.z); v.w = tf32r(v.w);
    ((float4*)g_wt)[(size_t)z * D_MODEL * D_MODEL / 4 + i] = v;
}

// ---------------------------------------------------------------------------
// Tensor-core GEMM via single-pass TF32 mma.sync.
// mode = mode_base + blockIdx.z: 0=Q(rope+scale,tf32 out) 1=K(rope,tf32 out)
//                                2=V(bf16 hi/lo out) 3=OUT(fp32 d_out)
// ---------------------------------------------------------------------------
#define NCHUNK      32
#define LDS_B       144                 // 128B data + 16B pad
#define ARR_BYTES   (128 * LDS_B)       // 18432
#define STAGE_BYTES (2 * ARR_BYTES)     // 36864 (A, B)
#define GEMM_SMEM   (2 * STAGE_BYTES)   // 73728 -> 2 CTAs/SM

__global__ __launch_bounds__(256, 2) void mma_gemm_kernel(float* __restrict__ outPtr,
                                                          int mode_base)
{
    extern __shared__ char smem[];
    const uint32_t sb = smem_u32(smem);
    const int tid = threadIdx.x;
    const int lane = tid & 31;
    const int warp = tid >> 5;
    const int mode = mode_base + (int)blockIdx.z;
    const int m0 = blockIdx.y * 128;
    const int n0 = blockIdx.x * 128;

    const float* Asrc = (mode < 3) ? g_xt : g_attn;
    const float* Bsrc = g_wt + (size_t)mode * D_MODEL * D_MODEL;

    const int arr = tid >> 7;                 // 0=A 1=B
    const int tt  = tid & 127;
    const float* srcBase = arr ? Bsrc : Asrc;
    const int rbase = arr ? n0 : m0;

    auto issue_chunk = [&](int chunk, int stage) {
        const uint32_t sdst = sb + stage * STAGE_BYTES + arr * ARR_BYTES;
        const int k0 = chunk * 32;
#pragma unroll
        for (int j = 0; j < 8; j++) {
            int idx = tt + j * 128;
            int row = idx >> 3;
            int blk = idx & 7;
            const void* g = srcBase + (size_t)(rbase + row) * D_MODEL + k0 + blk * 4;
            cp16(sdst + (uint32_t)(row * LDS_B + blk * 16), g);
        }
    };

    const int warpM = (warp & 1) * 64;
    const int warpN = (warp >> 1) * 32;

    const uint32_t aoff = (uint32_t)((warpM + (lane & 15)) * LDS_B + ((lane >> 4) << 4));
    const uint32_t boff = (uint32_t)((warpN + (lane & 7) + ((lane >> 4) << 3)) * LDS_B
                                     + (((lane >> 3) & 1) << 4));

    float acc[4][4][4];
#pragma unroll
    for (int mf = 0; mf < 4; mf++)
#pragma unroll
        for (int nf = 0; nf < 4; nf++)
#pragma unroll
            for (int c = 0; c < 4; c++) acc[mf][nf][c] = 0.0f;

    issue_chunk(0, 0);
    cp_commit();

    for (int i = 0; i < NCHUNK; i++) {
        const int stage = i & 1;
        cp_wait0();
        __syncthreads();

        const uint32_t aB = sb + stage * STAGE_BYTES + aoff;
        const uint32_t bB = sb + stage * STAGE_BYTES + ARR_BYTES + boff;

        uint32_t a4[4][4], b4[2][4];
#pragma unroll
        for (int mf = 0; mf < 4; mf++) ldsm4(a4[mf], aB + (uint32_t)(mf * 16 * LDS_B));
#pragma unroll
        for (int np = 0; np < 2; np++)  ldsm4(b4[np], bB + (uint32_t)(np * 16 * LDS_B));

        if (i + 1 < NCHUNK) {
            issue_chunk(i + 1, (i + 1) & 1);
            cp_commit();
        }

#pragma unroll
        for (int ks = 0; ks < 4; ks++) {
            if (ks > 0) {
                const uint32_t kb = (uint32_t)(ks * 32);
#pragma unroll
                for (int mf = 0; mf < 4; mf++)
                    ldsm4(a4[mf], aB + (uint32_t)(mf * 16 * LDS_B) + kb);
#pragma unroll
                for (int np = 0; np < 2; np++)
                    ldsm4(b4[np], bB + (uint32_t)(np * 16 * LDS_B) + kb);
            }
#pragma unroll
            for (int mf = 0; mf < 4; mf++)
#pragma unroll
                for (int nf = 0; nf < 4; nf++) {
                    const int np = nf >> 1, sub = (nf & 1) * 2;
                    mma_tf32(acc[mf][nf], a4[mf], b4[np][sub], b4[np][sub + 1]);
                }
        }
    }

#pragma unroll
    for (int mf = 0; mf < 4; mf++) {
#pragma unroll
        for (int nf = 0; nf < 4; nf++) {
            const int m = m0 + warpM + mf * 16 + (lane >> 2);
            const int n = n0 + warpN + nf * 8 + (lane & 3) * 2;
#pragma unroll
            for (int half = 0; half < 2; half++) {
                const int mm = m + half * 8;
                float v0 = acc[mf][nf][half * 2];
                float v1 = acc[mf][nf][half * 2 + 1];
                if (mode == 3) {
                    *(float2*)(outPtr + (size_t)mm * D_MODEL + n) = make_float2(v0, v1);
                } else {
                    const int b = mm >> 11;
                    const int s = mm & 2047;
                    const int h = n >> 6;
                    const int dh = n & 63;
                    if (mode < 2) {
                        const int pi = dh >> 1;
                        float co = g_cos[s * 32 + pi];
                        float sn = g_sin[s * 32 + pi];
                        float r0 = v0 * co - v1 * sn;
                        float r1 = v0 * sn + v1 * co;
                        v0 = r0; v1 = r1;
                    }
                    size_t o = ((size_t)(b * NUM_HEADS + h) * SEQ + s) * D_HEAD + dh;
                    if (mode == 0) {
                        *(float2*)&g_qt[o] = make_float2(tf32r(v0 * 0.125f),
                                                         tf32r(v1 * 0.125f));
                    } else if (mode == 1) {
                        *(float2*)&g_kt[o] = make_float2(tf32r(v0), tf32r(v1));
                    } else {
                        __nv_bfloat16 h0 = __float2bfloat16(v0);
                        __nv_bfloat16 h1 = __float2bfloat16(v1);
                        __nv_bfloat162 hp; hp.x = h0; hp.y = h1;
                        __nv_bfloat162 lp;
                        lp.x = __float2bfloat16(v0 - __bfloat162float(h0));
                        lp.y = __float2bfloat16(v1 - __bfloat162float(h1));
                        *(__nv_bfloat162*)&g_vh[o] = hp;
                        *(__nv_bfloat162*)&g_vl[o] = lp;
                    }
                }
            }
        }
    }
}

// ---------------------------------------------------------------------------
// Tensor-core causal flash attention, 64 q-rows per CTA (128 threads, 4 warps).
// S = Q K^T in single-pass TF32 (Q/K tf32 fp32); P.V in 3-term bf16.
// Stage: K fp32 (17408B) + Vh (9216) + Vl (9216) = 35840 <= 36864.
// Q staged through stage-0 K area. 73.7KB smem -> 3 CTAs/SM.
// ---------------------------------------------------------------------------
#define ATT_LDSK  272                   // 256B fp32 row + 16B pad
#define ATT_LDSV  144                   // 128B bf16 row + 16B pad
#define ATT_KB    (64 * ATT_LDSK)       // 17408
#define ATT_VB    (64 * ATT_LDSV)       // 9216
#define ATT_VOFF0 ATT_KB                // Vh offset within stage
#define ATT_VOFF1 (ATT_KB + ATT_VB)     // Vl offset
#define ATT_STAGE 36864
#define ATT_SMEM  (2 * ATT_STAGE)       // 73728 -> 3 CTAs/SM

__global__ __launch_bounds__(128, 3) void attn_mma_kernel() {
    extern __shared__ char smem[];
    const uint32_t sb = smem_u32(smem);
    const int tid = threadIdx.x;
    const int lane = tid & 31;
    const int warp = tid >> 5;            // 0..3
    const int bh = blockIdx.y;
    const int qtile = (int)gridDim.x - 1 - (int)blockIdx.x;   // longest first
    const int q0 = qtile * 64;

    const size_t bhoff = (size_t)bh * SEQ * D_HEAD;

    // ---- Stage Q (fp32) into stage-0 K area: 64 rows x 256B = 1024 x 16B ----
#pragma unroll
    for (int j = 0; j < 8; j++) {
        int idx = tid + j * 128;
        int row = idx >> 4, blk = idx & 15;
        cp16(sb + (uint32_t)(row * ATT_LDSK + blk * 16),
             g_qt + bhoff + (size_t)(q0 + row) * D_HEAD + blk * 4);
    }
    cp_commit();
    cp_wait0();
    __syncthreads();

    // Q tf32 A-fragments (persist): 8 k8 steps
    uint32_t qf[8][4];
    const uint32_t aoffQ = (uint32_t)((warp * 16 + (lane & 15)) * ATT_LDSK
                                      + ((lane >> 4) << 4));
#pragma unroll
    for (int ks = 0; ks < 8; ks++)
        ldsm4(qf[ks], sb + aoffQ + ks * 32);
    __syncthreads();     // all warps done reading Q before KV0 overwrites

    // K/V loader: K by 64 threads (16 cp16), Vh/Vl by 32 threads each
    const int arr = tid >> 5;
    const int tt  = tid & 31;
    const int tt2 = tid & 63;
    auto issue_kv = [&](int t, int stage) {
        const uint32_t dstS = sb + (uint32_t)(stage * ATT_STAGE);
        const int k0 = t * 64;
        if (arr < 2) {        // K fp32: 1024 x 16B
#pragma unroll
            for (int j = 0; j < 16; j++) {
                int idx = tt2 + j * 64;
                int row = idx >> 4, blk = idx & 15;
                cp16(dstS + (uint32_t)(row * ATT_LDSK + blk * 16),
                     g_kt + bhoff + (size_t)(k0 + row) * D_HEAD + blk * 4);
            }
        } else {              // Vh/Vl bf16: 512 x 16B
            const __nv_bfloat16* vsrc = ((arr == 2) ? g_vh : g_vl) + bhoff;
            const uint32_t vb = dstS + (uint32_t)((arr == 2) ? ATT_VOFF0 : ATT_VOFF1);
#pragma unroll
            for (int j = 0; j < 16; j++) {
                int idx = tt + j * 32;    // 0..511
                int row = idx >> 3, blk = idx & 7;
                cp16(vb + (uint32_t)(row * ATT_LDSV + blk * 16),
                     vsrc + (size_t)(k0 + row) * D_HEAD + blk * 8);
            }
        }
    };
    issue_kv(0, 0);
    cp_commit();

    float o[8][4];
#pragma unroll
    for (int nf = 0; nf < 8; nf++)
#pragma unroll
        for (int c = 0; c < 4; c++) o[nf][c] = 0.0f;
    float m0 = -1e30f, m1 = -1e30f, l0 = 0.0f, l1 = 0.0f;

    const int fullTiles = q0 >> 6;
    const int nTiles = fullTiles + 1;
    const int rw0 = q0 + warp * 16 + (lane >> 2);

    const uint32_t boffK = (uint32_t)(((lane & 7) + ((lane >> 4) << 3)) * ATT_LDSK
                                      + (((lane >> 3) & 1) << 4));
    const uint32_t voff  = (uint32_t)((lane & 15) * ATT_LDSV + ((lane >> 4) << 4));

    for (int t = 0; t < nTiles; t++) {
        const int stage = t & 1;
        const int k0 = t * 64;
        cp_wait0();
        __syncthreads();
        if (t + 1 < nTiles) {
            issue_kv(t + 1, (t + 1) & 1);
            cp_commit();
        }

        {
            const uint32_t kS  = sb + (uint32_t)(stage * ATT_STAGE);
            const uint32_t vhS = kS + ATT_VOFF0;
            const uint32_t vlS = kS + ATT_VOFF1;

            // ---- S = Q K^T (single-pass TF32) ----
            float s[8][4];
#pragma unroll
            for (int nf = 0; nf < 8; nf++)
#pragma unroll
                for (int c = 0; c < 4; c++) s[nf][c] = 0.0f;

#pragma unroll
            for (int ks = 0; ks < 8; ks++) {      // k8 steps over d
                uint32_t k4[4][4];
#pragma unroll
                for (int np = 0; np < 4; np++)
                    ldsm4(k4[np], kS + (uint32_t)(np * 16 * ATT_LDSK) + ks * 32 + boffK);
#pragma unroll
                for (int np = 0; np < 4; np++) {
                    mma_tf32(s[np * 2],     qf[ks], k4[np][0], k4[np][1]);
                    mma_tf32(s[np * 2 + 1], qf[ks], k4[np][2], k4[np][3]);
                }
            }

            // ---- causal mask (diagonal tile only) ----
            if (t == fullTiles) {
#pragma unroll
                for (int nf = 0; nf < 8; nf++) {
                    int kg = k0 + nf * 8 + (lane & 3) * 2;
#pragma unroll
                    for (int c = 0; c < 4; c++) {
                        int kk = kg + (c & 1);
                        int qq = rw0 + ((c >> 1) << 3);
                        if (kk > qq) s[nf][c] = -1e30f;
                    }
                }
            }

            // ---- online softmax ----
            float mx0 = s[0][0], mx1 = s[0][2];
#pragma unroll
            for (int nf = 0; nf < 8; nf++) {
                mx0 = fmaxf(mx0, fmaxf(s[nf][0], s[nf][1]));
                mx1 = fmaxf(mx1, fmaxf(s[nf][2], s[nf][3]));
            }
            mx0 = fmaxf(mx0, __shfl_xor_sync(0xFFFFFFFFu, mx0, 1));
            mx0 = fmaxf(mx0, __shfl_xor_sync(0xFFFFFFFFu, mx0, 2));
            mx1 = fmaxf(mx1, __shfl_xor_sync(0xFFFFFFFFu, mx1, 1));
            mx1 = fmaxf(mx1, __shfl_xor_sync(0xFFFFFFFFu, mx1, 2));
            float nm0 = fmaxf(m0, mx0), nm1 = fmaxf(m1, mx1);
            float al0 = __expf(m0 - nm0), al1 = __expf(m1 - nm1);
            m0 = nm0; m1 = nm1;
            l0 *= al0; l1 *= al1;
#pragma unroll
            for (int nf = 0; nf < 8; nf++) {
                o[nf][0] *= al0; o[nf][1] *= al0;
                o[nf][2] *= al1; o[nf][3] *= al1;
            }

            float rs0 = 0.0f, rs1 = 0.0f;
            uint32_t ph[4][4], pl[4][4];
#pragma unroll
            for (int nf = 0; nf < 8; nf++) {
                float p0 = __expf(s[nf][0] - m0);
                float p1 = __expf(s[nf][1] - m0);
                float p2 = __expf(s[nf][2] - m1);
                float p3 = __expf(s[nf][3] - m1);
                rs0 += p0 + p1;
                rs1 += p2 + p3;
                const int ks = nf >> 1, i0 = (nf & 1) * 2;
                uint32_t h01 = pack_bf16(p0, p1);
                uint32_t h23 = pack_bf16(p2, p3);
                ph[ks][i0]     = h01;
                ph[ks][i0 + 1] = h23;
                __nv_bfloat162 hb01 = *(__nv_bfloat162*)&h01;
                __nv_bfloat162 hb23 = *(__nv_bfloat162*)&h23;
                pl[ks][i0]     = pack_bf16(p0 - __bfloat162float(hb01.x),
                                           p1 - __bfloat162float(hb01.y));
                pl[ks][i0 + 1] = pack_bf16(p2 - __bfloat162float(hb23.x),
                                           p3 - __bfloat162float(hb23.y));
            }
            rs0 += __shfl_xor_sync(0xFFFFFFFFu, rs0, 1);
            rs0 += __shfl_xor_sync(0xFFFFFFFFu, rs0, 2);
            rs1 += __shfl_xor_sync(0xFFFFFFFFu, rs1, 1);
            rs1 += __shfl_xor_sync(0xFFFFFFFFu, rs1, 2);
            l0 += rs0; l1 += rs1;

            // ---- O += P V (3-term bf16; V via trans ldmatrix) ----
#pragma unroll
            for (int ks = 0; ks < 4; ks++) {
                uint32_t vh4[4][4], vl4[4][4];
#pragma unroll
                for (int np = 0; np < 4; np++) {
                    ldsm4t(vh4[np], vhS + (uint32_t)(ks * 16 * ATT_LDSV) + np * 32 + voff);
                    ldsm4t(vl4[np], vlS + (uint32_t)(ks * 16 * ATT_LDSV) + np * 32 + voff);
                }
#pragma unroll
                for (int np = 0; np < 4; np++) {
                    mma_bf16(o[np * 2],     ph[ks], vh4[np][0], vh4[np][1]);
                    mma_bf16(o[np * 2 + 1], ph[ks], vh4[np][2], vh4[np][3]);
                    mma_bf16(o[np * 2],     ph[ks], vl4[np][0], vl4[np][1]);
                    mma_bf16(o[np * 2 + 1], ph[ks], vl4[np][2], vl4[np][3]);
                    mma_bf16(o[np * 2],     pl[ks], vh4[np][0], vh4[np][1]);
                    mma_bf16(o[np * 2 + 1], pl[ks], vh4[np][2], vh4[np][3]);
                }
            }
        }
    }

    // ---- epilogue: normalize, tf32-round, store fp32 attn [B,S,H*64] ----
    float inv0 = 1.0f / l0, inv1 = 1.0f / l1;
    const int b = bh >> 4, h = bh & 15;
    const int r0 = q0 + warp * 16 + (lane >> 2);
    const size_t base0 = ((size_t)(b * SEQ + r0)) * D_MODEL + h * D_HEAD + (lane & 3) * 2;
    const size_t base1 = base0 + (size_t)8 * D_MODEL;
#pragma unroll
    for (int nf = 0; nf < 8; nf++) {
        float2 va = make_float2(tf32r(o[nf][0] * inv0), tf32r(o[nf][1] * inv0));
        float2 vb = make_float2(tf32r(o[nf][2] * inv1), tf32r(o[nf][3] * inv1));
        *(float2*)&g_attn[base0 + nf * 8] = va;
        *(float2*)&g_attn[base1 + nf * 8] = vb;
    }
}

// ---------------------------------------------------------------------------
// Launch
// ---------------------------------------------------------------------------
extern "C" void kernel_launch(void* const* d_in, const int* in_sizes, int n_in,
                              void* d_out, int out_size)
{
    const float* x   = (const float*)d_in[0];
    const int*   pos = (const int*)  d_in[1];
    const float* Wq  = (const float*)d_in[2];
    const float* Wk  = (const float*)d_in[3];
    const float* Wv  = (const float*)d_in[4];
    const float* Wo  = (const float*)d_in[5];
    float* out = (float*)d_out;

    cudaFuncSetAttribute(mma_gemm_kernel,
                         cudaFuncAttributeMaxDynamicSharedMemorySize, GEMM_SMEM);
    cudaFuncSetAttribute(attn_mma_kernel,
                         cudaFuncAttributeMaxDynamicSharedMemorySize, ATT_SMEM);

    rope_table_kernel<<<(SEQ * 32 + 255) / 256, 256>>>(pos);

    round_x_kernel<<<(MTOT * D_MODEL / 4 + 255) / 256, 256>>>(x);
    dim3 gw((D_MODEL * D_MODEL / 4 + 255) / 256, 4);
    round_w_kernel<<<gw, 256>>>(Wq, Wk, Wv, Wo);

    dim3 gq(D_MODEL / 128, MTOT / 128, 3);       // Q,K,V projections
    mma_gemm_kernel<<<gq, 256, GEMM_SMEM>>>(out, 0);

    dim3 ga(SEQ / 64, BATCH * NUM_HEADS);        // 64 q-rows per CTA
    attn_mma_kernel<<<ga, 128, ATT_SMEM>>>();

    dim3 go(D_MODEL / 128, MTOT / 128, 1);       // output projection
    mma_gemm_kernel<<<go, 256, GEMM_SMEM>>>(out, 3);
}